// round 1
// baseline (speedup 1.0000x reference)
#include <cuda_runtime.h>
#include <math.h>

#define S_LEN   2048
#define B_SZ    32
#define D_SZ    512
#define H_SZ    512
#define N3      1536            // 3*H
#define M_SZ    (S_LEN * B_SZ)  // 65536
#define K_SZ    512
#define CHUNK   32
#define NCHUNK  (S_LEN / CHUNK) // 64
#define NCH     (B_SZ * H_SZ)   // 16384
#define SSEG    16
#define SEGLEN  (S_LEN / SSEG)  // 128
#define C_SZ    10

// ---------------- scratch (device globals: allocation-free rule) ----------------
__device__ float g_hA[(size_t)M_SZ * H_SZ];   // 128 MB
__device__ float g_hB[(size_t)M_SZ * H_SZ];   // 128 MB
__device__ float g_U [(size_t)M_SZ * N3];     // 384 MB  (xt | f | r interleaved by column block)
__device__ float g_Ac[NCHUNK * NCH];
__device__ float g_Bc[NCHUNK * NCH];
__device__ float g_ci[NCHUNK * NCH];
__device__ float g_pm[SSEG * NCH];
__device__ float g_pool[NCH];

// ---------------- f32x2 packed helpers ----------------
__device__ __forceinline__ unsigned long long pack2(float x, float y) {
    unsigned long long r;
    asm("mov.b64 %0, {%1, %2};" : "=l"(r) : "f"(x), "f"(y));
    return r;
}
__device__ __forceinline__ float2 unpack2(unsigned long long v) {
    float2 r;
    asm("mov.b64 {%0, %1}, %2;" : "=f"(r.x), "=f"(r.y) : "l"(v));
    return r;
}
__device__ __forceinline__ void ffma2(unsigned long long& d,
                                      unsigned long long a,
                                      unsigned long long b) {
    asm("fma.rn.f32x2 %0, %1, %2, %0;" : "+l"(d) : "l"(a), "l"(b));
}

__device__ __forceinline__ float sigm(float x) { return 1.0f / (1.0f + expf(-x)); }

// ---------------- embedding gather ----------------
__global__ void gather_kernel(const int* __restrict__ x,
                              const float* __restrict__ embed,
                              float* __restrict__ h) {
    size_t idx = (size_t)blockIdx.x * blockDim.x + threadIdx.x; // M_SZ * 128 float4 slots
    int m = (int)(idx >> 7);
    int j = (int)(idx & 127);
    int row = x[m];
    reinterpret_cast<float4*>(h)[(size_t)m * 128 + j] =
        reinterpret_cast<const float4*>(embed)[(size_t)row * 128 + j];
}

// ---------------- fused GEMM + gate epilogue ----------------
// U[m, 0:512)   = xt
// U[m, 512:1024)= f = sigmoid(u + bf)
// U[m,1024:1536)= r = sigmoid(u + br)      bias index for both gate segments = n - 512
#define BM 128
#define BN 128
#define BK 16

__global__ __launch_bounds__(256, 2) void gemm_fused_kernel(
    const float* __restrict__ A,    // M x 512
    const float* __restrict__ Bg,   // 512 x 1536
    const float* __restrict__ bias, // 1024
    float* __restrict__ U)          // M x 1536
{
    __shared__ float As[2][BK][BM + 4];
    __shared__ float Bs[2][BK][BN];

    const int tid = threadIdx.x;
    const int tx = tid & 15;
    const int ty = tid >> 4;
    const int bn = blockIdx.x;
    const int bm = blockIdx.y;

    const int aRow = tid >> 2;        // 0..63
    const int aCol = (tid & 3) * 4;   // 0,4,8,12
    const int bRow = tid >> 5;        // 0..7
    const int bCol = (tid & 31) * 4;  // 0..124

    const float* Aptr = A + ((size_t)(bm * BM + aRow)) * K_SZ + aCol;
    const float* Bptr = Bg + (size_t)bRow * N3 + bn * BN + bCol;

    unsigned long long acc[8][4];
#pragma unroll
    for (int i = 0; i < 8; i++)
#pragma unroll
        for (int j = 0; j < 4; j++) acc[i][j] = 0ULL;

    // prologue: tile 0 -> buffer 0
    {
        float4 a0 = *reinterpret_cast<const float4*>(Aptr);
        float4 a1 = *reinterpret_cast<const float4*>(Aptr + (size_t)64 * K_SZ);
        float4 b0 = *reinterpret_cast<const float4*>(Bptr);
        float4 b1 = *reinterpret_cast<const float4*>(Bptr + (size_t)8 * N3);
        As[0][aCol + 0][aRow] = a0.x; As[0][aCol + 1][aRow] = a0.y;
        As[0][aCol + 2][aRow] = a0.z; As[0][aCol + 3][aRow] = a0.w;
        As[0][aCol + 0][aRow + 64] = a1.x; As[0][aCol + 1][aRow + 64] = a1.y;
        As[0][aCol + 2][aRow + 64] = a1.z; As[0][aCol + 3][aRow + 64] = a1.w;
        *reinterpret_cast<float4*>(&Bs[0][bRow][bCol]) = b0;
        *reinterpret_cast<float4*>(&Bs[0][bRow + 8][bCol]) = b1;
    }
    __syncthreads();

    const int NT = K_SZ / BK; // 32
    for (int t = 0; t < NT; t++) {
        const int cur = t & 1;
        float4 na0, na1, nb0, nb1;
        if (t + 1 < NT) {
            const float* Ap = Aptr + (size_t)(t + 1) * BK;
            na0 = *reinterpret_cast<const float4*>(Ap);
            na1 = *reinterpret_cast<const float4*>(Ap + (size_t)64 * K_SZ);
            const float* Bp = Bptr + (size_t)(t + 1) * BK * N3;
            nb0 = *reinterpret_cast<const float4*>(Bp);
            nb1 = *reinterpret_cast<const float4*>(Bp + (size_t)8 * N3);
        }

#pragma unroll
        for (int k = 0; k < BK; k++) {
            float4 af0 = *reinterpret_cast<const float4*>(&As[cur][k][ty * 8]);
            float4 af1 = *reinterpret_cast<const float4*>(&As[cur][k][ty * 8 + 4]);
            float4 bf0 = *reinterpret_cast<const float4*>(&Bs[cur][k][tx * 8]);
            float4 bf1 = *reinterpret_cast<const float4*>(&Bs[cur][k][tx * 8 + 4]);
            unsigned long long bb0 = pack2(bf0.x, bf0.y);
            unsigned long long bb1 = pack2(bf0.z, bf0.w);
            unsigned long long bb2 = pack2(bf1.x, bf1.y);
            unsigned long long bb3 = pack2(bf1.z, bf1.w);
            float av[8] = {af0.x, af0.y, af0.z, af0.w, af1.x, af1.y, af1.z, af1.w};
#pragma unroll
            for (int mi = 0; mi < 8; mi++) {
                unsigned long long a2 = pack2(av[mi], av[mi]);
                ffma2(acc[mi][0], a2, bb0);
                ffma2(acc[mi][1], a2, bb1);
                ffma2(acc[mi][2], a2, bb2);
                ffma2(acc[mi][3], a2, bb3);
            }
        }

        if (t + 1 < NT) {
            const int nxt = cur ^ 1;
            As[nxt][aCol + 0][aRow] = na0.x; As[nxt][aCol + 1][aRow] = na0.y;
            As[nxt][aCol + 2][aRow] = na0.z; As[nxt][aCol + 3][aRow] = na0.w;
            As[nxt][aCol + 0][aRow + 64] = na1.x; As[nxt][aCol + 1][aRow + 64] = na1.y;
            As[nxt][aCol + 2][aRow + 64] = na1.z; As[nxt][aCol + 3][aRow + 64] = na1.w;
            *reinterpret_cast<float4*>(&Bs[nxt][bRow][bCol]) = nb0;
            *reinterpret_cast<float4*>(&Bs[nxt][bRow + 8][bCol]) = nb1;
        }
        __syncthreads();
    }

    // epilogue
    const int row0 = bm * BM + ty * 8;
    const int n0 = bn * BN + tx * 8;
    const bool isGate = (n0 >= 512);
    float2 bv[4];
    if (isGate) {
        const float2* bp = reinterpret_cast<const float2*>(bias + n0 - 512);
#pragma unroll
        for (int j = 0; j < 4; j++) bv[j] = bp[j];
    }
#pragma unroll
    for (int mi = 0; mi < 8; mi++) {
        size_t base = (size_t)(row0 + mi) * N3 + n0;
#pragma unroll
        for (int nj = 0; nj < 4; nj++) {
            float2 v = unpack2(acc[mi][nj]);
            if (isGate) {
                v.x = sigm(v.x + bv[nj].x);
                v.y = sigm(v.y + bv[nj].y);
            }
            *reinterpret_cast<float2*>(&U[base + 2 * nj]) = v;
        }
    }
}

// ---------------- scan pass A: per-chunk affine composition ----------------
__global__ void scan_passA(const float* __restrict__ U,
                           float* __restrict__ Ac, float* __restrict__ Bc) {
    int idx = blockIdx.x * blockDim.x + threadIdx.x; // NCHUNK*NCH
    int ch = idx & (NCH - 1);
    int chunk = idx >> 14;
    int b = ch >> 9;
    int h = ch & 511;
    const float* fp = U + ((size_t)(chunk * CHUNK * B_SZ + b)) * N3 + 512 + h;
    float Aa = 1.0f, Bb = 0.0f;
#pragma unroll 8
    for (int i = 0; i < CHUNK; i++) {
        float f  = fp[0];
        float xt = fp[-512];
        Bb = f * Bb + (1.0f - f) * xt;
        Aa *= f;
        fp += (size_t)B_SZ * N3;
    }
    Ac[idx] = Aa;
    Bc[idx] = Bb;
}

// ---------------- scan pass B: prefix over chunks ----------------
__global__ void scan_passB(const float* __restrict__ Ac,
                           const float* __restrict__ Bc,
                           float* __restrict__ ci) {
    int ch = blockIdx.x * blockDim.x + threadIdx.x; // NCH
    float c = 0.0f;
#pragma unroll 8
    for (int k = 0; k < NCHUNK; k++) {
        ci[k * NCH + ch] = c;
        c = Ac[k * NCH + ch] * c + Bc[k * NCH + ch];
    }
}

// ---------------- scan pass C: rescan + highway output (fused) ----------------
__global__ void scan_passC(const float* __restrict__ U,
                           const float* __restrict__ ci,
                           const float* __restrict__ hin,
                           float* __restrict__ hout) {
    int idx = blockIdx.x * blockDim.x + threadIdx.x;
    int ch = idx & (NCH - 1);
    int chunk = idx >> 14;
    int b = ch >> 9;
    int h = ch & 511;
    size_t m0 = (size_t)(chunk * CHUNK * B_SZ + b);
    const float* fp = U + m0 * N3 + 512 + h;
    const float* hi = hin + m0 * H_SZ + h;
    float* ho = hout + m0 * H_SZ + h;
    float c = ci[idx];
#pragma unroll 4
    for (int i = 0; i < CHUNK; i++) {
        float f  = fp[0];
        float xt = fp[-512];
        float r  = fp[512];
        float hv = hi[0];
        c = f * c + (1.0f - f) * xt;
        ho[0] = r * tanhf(c) + (1.0f - r) * hv;
        fp += (size_t)B_SZ * N3;
        hi += (size_t)B_SZ * H_SZ;
        ho += (size_t)B_SZ * H_SZ;
    }
}

// ---------------- max pool (tanh is monotonic: pool raw h, tanh after) ----------------
__global__ void pool_partial(const float* __restrict__ hf, float* __restrict__ pm) {
    int idx = blockIdx.x * blockDim.x + threadIdx.x; // SSEG*NCH
    int ch = idx & (NCH - 1);
    int seg = idx >> 14;
    int b = ch >> 9;
    int h = ch & 511;
    const float* p = hf + ((size_t)(seg * SEGLEN * B_SZ + b)) * H_SZ + h;
    float mx = -INFINITY;
#pragma unroll 8
    for (int i = 0; i < SEGLEN; i++) {
        mx = fmaxf(mx, p[0]);
        p += (size_t)B_SZ * H_SZ;
    }
    pm[idx] = mx;
}

__global__ void pool_reduce(const float* __restrict__ pm, float* __restrict__ pool) {
    int ch = blockIdx.x * blockDim.x + threadIdx.x; // NCH
    float mx = -INFINITY;
#pragma unroll
    for (int s = 0; s < SSEG; s++) mx = fmaxf(mx, pm[s * NCH + ch]);
    pool[ch] = tanhf(tanhf(mx));
}

// ---------------- tiny classifier: (32,512) @ (512,10) + bias ----------------
__global__ void classifier_kernel(const float* __restrict__ pool,
                                  const float* __restrict__ Wc,
                                  const float* __restrict__ bc,
                                  float* __restrict__ out) {
    int tid = threadIdx.x; // 320
    int b = tid / C_SZ;
    int c = tid % C_SZ;
    float s = bc[c];
    const float* p = pool + b * H_SZ;
#pragma unroll 8
    for (int h = 0; h < H_SZ; h++) s += p[h] * Wc[h * C_SZ + c];
    out[b * C_SZ + c] = s;
}

// ---------------- launch ----------------
extern "C" void kernel_launch(void* const* d_in, const int* in_sizes, int n_in,
                              void* d_out, int out_size) {
    const int*   x     = (const int*)d_in[0];
    const float* embed = (const float*)d_in[1];
    const float* W     = (const float*)d_in[2]; // (L, 512, 1536)
    const float* b     = (const float*)d_in[3]; // (L, 1024)
    const float* Wc    = (const float*)d_in[4]; // (512, 10)
    const float* bc    = (const float*)d_in[5]; // (10,)
    float* out = (float*)d_out;

    float *hA, *hB, *U, *Ac, *Bc, *ci, *pm, *pool;
    cudaGetSymbolAddress((void**)&hA, g_hA);
    cudaGetSymbolAddress((void**)&hB, g_hB);
    cudaGetSymbolAddress((void**)&U,  g_U);
    cudaGetSymbolAddress((void**)&Ac, g_Ac);
    cudaGetSymbolAddress((void**)&Bc, g_Bc);
    cudaGetSymbolAddress((void**)&ci, g_ci);
    cudaGetSymbolAddress((void**)&pm, g_pm);
    cudaGetSymbolAddress((void**)&pool, g_pool);

    // 1) embedding gather
    gather_kernel<<<(M_SZ * 128) / 256, 256>>>(x, embed, hA);

    dim3 gemmGrid(N3 / BN, M_SZ / BM); // (12, 512)
    const int scanBlocks = (NCHUNK * NCH) / 256; // 4096

    // 2) layer 0: hA -> hB
    gemm_fused_kernel<<<gemmGrid, 256>>>(hA, W, b, U);
    scan_passA<<<scanBlocks, 256>>>(U, Ac, Bc);
    scan_passB<<<NCH / 256, 256>>>(Ac, Bc, ci);
    scan_passC<<<scanBlocks, 256>>>(U, ci, hA, hB);

    // 3) layer 1: hB -> hA
    gemm_fused_kernel<<<gemmGrid, 256>>>(hB, W + (size_t)D_SZ * N3, b + 2 * H_SZ, U);
    scan_passA<<<scanBlocks, 256>>>(U, Ac, Bc);
    scan_passB<<<NCH / 256, 256>>>(Ac, Bc, ci);
    scan_passC<<<scanBlocks, 256>>>(U, ci, hB, hA);

    // 4) pool + classifier
    pool_partial<<<(SSEG * NCH) / 256, 256>>>(hA, pm);
    pool_reduce<<<NCH / 256, 256>>>(pm, pool);
    classifier_kernel<<<1, B_SZ * C_SZ>>>(pool, Wc, bc, out);
}

// round 3
// speedup vs baseline: 1.7361x; 1.7361x over previous
#include <cuda_runtime.h>
#include <cuda_bf16.h>
#include <math.h>
#include <stdint.h>

#define S_LEN   2048
#define B_SZ    32
#define D_SZ    512
#define H_SZ    512
#define N3      1536            // 3*H
#define M_SZ    (S_LEN * B_SZ)  // 65536
#define K_SZ    512
#define CHUNK   32
#define NCHUNK  (S_LEN / CHUNK) // 64
#define NCH     (B_SZ * H_SZ)   // 16384
#define SSEG    16
#define SEGLEN  (S_LEN / SSEG)  // 128
#define C_SZ    10

// ---------------- GEMM tiling ----------------
#define BM 128
#define BN 128
#define BK 32
#define KT_ITERS (K_SZ / BK)    // 16
#define STAGES 4
#define MTILES (M_SZ / BM)      // 512
#define NTILES (N3 / BN)        // 12

// smem pitches (bytes), padded for conflict-free ldmatrix
#define A_PITCH 80              // 32 bf16 = 64B + 16B pad
#define B_PITCH 272             // 128 bf16 = 256B + 16B pad
#define ST_A_HI 0
#define ST_A_LO (BM * A_PITCH)                 // 10240
#define ST_B_HI (2 * BM * A_PITCH)             // 20480
#define ST_B_LO (2 * BM * A_PITCH + BK * B_PITCH)  // 29184
#define ST_BYTES (2 * BM * A_PITCH + 2 * BK * B_PITCH) // 37888
#define DYN_SMEM (STAGES * ST_BYTES)           // 151552

// ---------------- scratch (device globals: allocation-free rule) ----------------
__device__ float          g_hA[(size_t)M_SZ * H_SZ];   // 128 MB
__device__ float          g_hB[(size_t)M_SZ * H_SZ];   // 128 MB
__device__ float          g_U [(size_t)M_SZ * N3];     // 384 MB
__device__ __nv_bfloat16  g_Ahi[(size_t)M_SZ * K_SZ];  // 64 MB
__device__ __nv_bfloat16  g_Alo[(size_t)M_SZ * K_SZ];  // 64 MB
__device__ __nv_bfloat16  g_Bhi[2 * K_SZ * N3];        // 3 MB
__device__ __nv_bfloat16  g_Blo[2 * K_SZ * N3];        // 3 MB
__device__ float          g_Ac[NCHUNK * NCH];
__device__ float          g_Bc[NCHUNK * NCH];
__device__ float          g_ci[NCHUNK * NCH];
__device__ float          g_pm[SSEG * NCH];
__device__ float          g_pool[NCH];

// ---------------- PTX helpers ----------------
__device__ __forceinline__ uint32_t smem_u32(const void* p) {
    uint32_t a;
    asm("{ .reg .u64 t; cvta.to.shared.u64 t, %1; cvt.u32.u64 %0, t; }" : "=r"(a) : "l"(p));
    return a;
}

__device__ __forceinline__ void cp16(uint32_t dst, const void* src) {
    asm volatile("cp.async.cg.shared.global [%0], [%1], 16;" :: "r"(dst), "l"(src));
}
#define CP_COMMIT() asm volatile("cp.async.commit_group;" ::: "memory")
#define CP_WAIT(n)  asm volatile("cp.async.wait_group %0;" :: "n"(n) : "memory")

__device__ __forceinline__ void ldsm_x4(uint32_t& r0, uint32_t& r1, uint32_t& r2, uint32_t& r3,
                                        uint32_t addr) {
    asm volatile("ldmatrix.sync.aligned.m8n8.x4.shared.b16 {%0,%1,%2,%3}, [%4];"
                 : "=r"(r0), "=r"(r1), "=r"(r2), "=r"(r3) : "r"(addr));
}
__device__ __forceinline__ void ldsm_x4_t(uint32_t& r0, uint32_t& r1, uint32_t& r2, uint32_t& r3,
                                          uint32_t addr) {
    asm volatile("ldmatrix.sync.aligned.m8n8.x4.trans.shared.b16 {%0,%1,%2,%3}, [%4];"
                 : "=r"(r0), "=r"(r1), "=r"(r2), "=r"(r3) : "r"(addr));
}

__device__ __forceinline__ void mma_bf16(float& c0, float& c1, float& c2, float& c3,
                                         uint32_t a0, uint32_t a1, uint32_t a2, uint32_t a3,
                                         uint32_t b0, uint32_t b1) {
    asm volatile(
        "mma.sync.aligned.m16n8k16.row.col.f32.bf16.bf16.f32 "
        "{%0,%1,%2,%3}, {%4,%5,%6,%7}, {%8,%9}, {%0,%1,%2,%3};"
        : "+f"(c0), "+f"(c1), "+f"(c2), "+f"(c3)
        : "r"(a0), "r"(a1), "r"(a2), "r"(a3), "r"(b0), "r"(b1));
}

__device__ __forceinline__ float sigm(float x) { return 1.0f / (1.0f + expf(-x)); }

// ---------------- embedding gather ----------------
__global__ void gather_kernel(const int* __restrict__ x,
                              const float* __restrict__ embed,
                              float* __restrict__ h) {
    size_t idx = (size_t)blockIdx.x * blockDim.x + threadIdx.x;
    int m = (int)(idx >> 7);
    int j = (int)(idx & 127);
    int row = x[m];
    reinterpret_cast<float4*>(h)[(size_t)m * 128 + j] =
        reinterpret_cast<const float4*>(embed)[(size_t)row * 128 + j];
}

// ---------------- conversions: fp32 -> bf16 hi/lo (identity layout) ----------------
__device__ __forceinline__ uint2 split_hi(float4 a, float4& rest) {
    __nv_bfloat16 h0 = __float2bfloat16_rn(a.x);
    __nv_bfloat16 h1 = __float2bfloat16_rn(a.y);
    __nv_bfloat16 h2 = __float2bfloat16_rn(a.z);
    __nv_bfloat16 h3 = __float2bfloat16_rn(a.w);
    rest.x = a.x - __bfloat162float(h0);
    rest.y = a.y - __bfloat162float(h1);
    rest.z = a.z - __bfloat162float(h2);
    rest.w = a.w - __bfloat162float(h3);
    __nv_bfloat162 p0 = __halves2bfloat162(h0, h1);
    __nv_bfloat162 p1 = __halves2bfloat162(h2, h3);
    uint2 r;
    r.x = *reinterpret_cast<uint32_t*>(&p0);
    r.y = *reinterpret_cast<uint32_t*>(&p1);
    return r;
}
__device__ __forceinline__ uint2 pack_bf4(float4 a) {
    __nv_bfloat162 p0 = __halves2bfloat162(__float2bfloat16_rn(a.x), __float2bfloat16_rn(a.y));
    __nv_bfloat162 p1 = __halves2bfloat162(__float2bfloat16_rn(a.z), __float2bfloat16_rn(a.w));
    uint2 r;
    r.x = *reinterpret_cast<uint32_t*>(&p0);
    r.y = *reinterpret_cast<uint32_t*>(&p1);
    return r;
}

__global__ void convert_kernel(const float* __restrict__ src,
                               __nv_bfloat16* __restrict__ hi,
                               __nv_bfloat16* __restrict__ lo) {
    size_t idx = (size_t)blockIdx.x * blockDim.x + threadIdx.x;  // groups of 4 floats
    float4 a = reinterpret_cast<const float4*>(src)[idx];
    float4 rest;
    uint2 hw = split_hi(a, rest);
    uint2 lw = pack_bf4(rest);
    reinterpret_cast<uint2*>(hi)[idx] = hw;
    reinterpret_cast<uint2*>(lo)[idx] = lw;
}

// ---------------- bf16 HMMA GEMM: 128x128x512, 3-term split, fused gate ----------------
__global__ __launch_bounds__(256, 1) void gemm_mma_kernel(
    const __nv_bfloat16* __restrict__ Ahi, const __nv_bfloat16* __restrict__ Alo,
    const __nv_bfloat16* __restrict__ Bhi, const __nv_bfloat16* __restrict__ Blo,
    const float* __restrict__ bias,   // 1024 (f then r)
    float* __restrict__ U)
{
    extern __shared__ __align__(1024) char smem[];
    __shared__ float s_bias[BN];

    const int tid = threadIdx.x;
    const int lane = tid & 31;
    const int wid = tid >> 5;
    const int wm = wid >> 2;          // 0..1
    const int wn = wid & 3;           // 0..3
    const int ntile = blockIdx.x;
    const int mtile = blockIdx.y;
    const int n0 = ntile * BN;
    const int m0 = mtile * BM;
    const bool gate = (n0 >= 512);

    if (tid < BN) s_bias[tid] = gate ? bias[n0 - 512 + tid] : 0.0f;

    const uint32_t sbase = smem_u32(smem);

    // per-thread load coordinates (2 chunks of 16B per array per stage)
    // A: chunk c -> row c>>2, kq c&3 ; B: chunk c -> row c>>4, nq c&15
    const int c0i = tid, c1i = tid + 256;

#define LOAD_STAGE(kt, st) do {                                                    \
        uint32_t sb = sbase + (st) * ST_BYTES;                                     \
        int kk = (kt) * BK;                                                        \
        {   int am = c0i >> 2, ak = c0i & 3;                                       \
            cp16(sb + ST_A_HI + am * A_PITCH + ak * 16,                            \
                 Ahi + (size_t)(m0 + am) * K_SZ + kk + ak * 8);                    \
            cp16(sb + ST_A_LO + am * A_PITCH + ak * 16,                            \
                 Alo + (size_t)(m0 + am) * K_SZ + kk + ak * 8); }                  \
        {   int am = c1i >> 2, ak = c1i & 3;                                       \
            cp16(sb + ST_A_HI + am * A_PITCH + ak * 16,                            \
                 Ahi + (size_t)(m0 + am) * K_SZ + kk + ak * 8);                    \
            cp16(sb + ST_A_LO + am * A_PITCH + ak * 16,                            \
                 Alo + (size_t)(m0 + am) * K_SZ + kk + ak * 8); }                  \
        {   int bk = c0i >> 4, bq = c0i & 15;                                      \
            cp16(sb + ST_B_HI + bk * B_PITCH + bq * 16,                            \
                 Bhi + (size_t)(kk + bk) * N3 + n0 + bq * 8);                      \
            cp16(sb + ST_B_LO + bk * B_PITCH + bq * 16,                            \
                 Blo + (size_t)(kk + bk) * N3 + n0 + bq * 8); }                    \
        {   int bk = c1i >> 4, bq = c1i & 15;                                      \
            cp16(sb + ST_B_HI + bk * B_PITCH + bq * 16,                            \
                 Bhi + (size_t)(kk + bk) * N3 + n0 + bq * 8);                      \
            cp16(sb + ST_B_LO + bk * B_PITCH + bq * 16,                            \
                 Blo + (size_t)(kk + bk) * N3 + n0 + bq * 8); }                    \
    } while (0)

    float acc[4][4][4];
#pragma unroll
    for (int i = 0; i < 4; i++)
#pragma unroll
        for (int j = 0; j < 4; j++)
#pragma unroll
            for (int q = 0; q < 4; q++) acc[i][j][q] = 0.0f;

    // prologue: stages 0..2
    LOAD_STAGE(0, 0); CP_COMMIT();
    LOAD_STAGE(1, 1); CP_COMMIT();
    LOAD_STAGE(2, 2); CP_COMMIT();

    const int lrow = lane & 15;
    const int lcol8 = (lane >> 4) * 8;

    for (int kt = 0; kt < KT_ITERS; kt++) {
        const int st = kt & (STAGES - 1);
        CP_WAIT(2);
        __syncthreads();

        // prefetch next stage (overwrites stage computed at kt-1; safe: all
        // threads passed the barrier above, so compute(kt-1) is complete)
        if (kt + 3 < KT_ITERS) LOAD_STAGE(kt + 3, (kt + 3) & (STAGES - 1));
        CP_COMMIT();

        const uint32_t sb = sbase + st * ST_BYTES;
        const uint32_t sAhi = sb + ST_A_HI + (wm * 64 + lrow) * A_PITCH;
        const uint32_t sAlo = sb + ST_A_LO + (wm * 64 + lrow) * A_PITCH;
        const uint32_t sBhi = sb + ST_B_HI + lrow * B_PITCH + (wn * 32 + lcol8) * 2;
        const uint32_t sBlo = sb + ST_B_LO + lrow * B_PITCH + (wn * 32 + lcol8) * 2;

#pragma unroll
        for (int k16 = 0; k16 < 2; k16++) {
            uint32_t ah[4][4], al[4][4], bh[2][4], bl[2][4];
#pragma unroll
            for (int mi = 0; mi < 4; mi++) {
                uint32_t ao = mi * 16 * A_PITCH + (k16 * 16 + lcol8) * 2;
                ldsm_x4(ah[mi][0], ah[mi][1], ah[mi][2], ah[mi][3], sAhi + ao);
                ldsm_x4(al[mi][0], al[mi][1], al[mi][2], al[mi][3], sAlo + ao);
            }
#pragma unroll
            for (int nj = 0; nj < 2; nj++) {
                uint32_t bo = k16 * 16 * B_PITCH + nj * 16 * 2;
                ldsm_x4_t(bh[nj][0], bh[nj][1], bh[nj][2], bh[nj][3], sBhi + bo);
                ldsm_x4_t(bl[nj][0], bl[nj][1], bl[nj][2], bl[nj][3], sBlo + bo);
            }
#pragma unroll
            for (int mi = 0; mi < 4; mi++) {
#pragma unroll
                for (int n8 = 0; n8 < 4; n8++) {
                    float* c = acc[mi][n8];
                    uint32_t b0h = bh[n8 >> 1][(n8 & 1) * 2], b1h = bh[n8 >> 1][(n8 & 1) * 2 + 1];
                    uint32_t b0l = bl[n8 >> 1][(n8 & 1) * 2], b1l = bl[n8 >> 1][(n8 & 1) * 2 + 1];
                    mma_bf16(c[0], c[1], c[2], c[3],
                             ah[mi][0], ah[mi][1], ah[mi][2], ah[mi][3], b0h, b1h);
                    mma_bf16(c[0], c[1], c[2], c[3],
                             ah[mi][0], ah[mi][1], ah[mi][2], ah[mi][3], b0l, b1l);
                    mma_bf16(c[0], c[1], c[2], c[3],
                             al[mi][0], al[mi][1], al[mi][2], al[mi][3], b0h, b1h);
                }
            }
        }
        __syncthreads();
    }

    // ---- epilogue: bias + sigmoid on gate tiles, float2 stores ----
    const int g = lane >> 2;
    const int tig = lane & 3;
#pragma unroll
    for (int mi = 0; mi < 4; mi++) {
        int row = m0 + wm * 64 + mi * 16 + g;
#pragma unroll
        for (int n8 = 0; n8 < 4; n8++) {
            int coll = wn * 32 + n8 * 8 + tig * 2;
            float v0 = acc[mi][n8][0], v1 = acc[mi][n8][1];
            float v2 = acc[mi][n8][2], v3 = acc[mi][n8][3];
            if (gate) {
                float b0 = s_bias[coll], b1 = s_bias[coll + 1];
                v0 = sigm(v0 + b0); v1 = sigm(v1 + b1);
                v2 = sigm(v2 + b0); v3 = sigm(v3 + b1);
            }
            float2 p0 = {v0, v1}, p1 = {v2, v3};
            *reinterpret_cast<float2*>(&U[(size_t)row * N3 + n0 + coll]) = p0;
            *reinterpret_cast<float2*>(&U[(size_t)(row + 8) * N3 + n0 + coll]) = p1;
        }
    }
#undef LOAD_STAGE
}

// ---------------- scan pass A: per-chunk affine composition ----------------
__global__ void scan_passA(const float* __restrict__ U,
                           float* __restrict__ Ac, float* __restrict__ Bc) {
    int idx = blockIdx.x * blockDim.x + threadIdx.x;
    int ch = idx & (NCH - 1);
    int chunk = idx >> 14;
    int b = ch >> 9;
    int h = ch & 511;
    const float* fp = U + ((size_t)(chunk * CHUNK * B_SZ + b)) * N3 + 512 + h;
    float Aa = 1.0f, Bb = 0.0f;
#pragma unroll 8
    for (int i = 0; i < CHUNK; i++) {
        float f  = fp[0];
        float xt = fp[-512];
        Bb = f * Bb + (1.0f - f) * xt;
        Aa *= f;
        fp += (size_t)B_SZ * N3;
    }
    Ac[idx] = Aa;
    Bc[idx] = Bb;
}

// ---------------- scan pass B: prefix over chunks ----------------
__global__ void scan_passB(const float* __restrict__ Ac,
                           const float* __restrict__ Bc,
                           float* __restrict__ ci) {
    int ch = blockIdx.x * blockDim.x + threadIdx.x;
    float c = 0.0f;
#pragma unroll 8
    for (int k = 0; k < NCHUNK; k++) {
        ci[k * NCH + ch] = c;
        c = Ac[k * NCH + ch] * c + Bc[k * NCH + ch];
    }
}

// ---------------- scan pass C: rescan + highway output ----------------
__global__ void scan_passC(const float* __restrict__ U,
                           const float* __restrict__ ci,
                           const float* __restrict__ hin,
                           float* __restrict__ hout) {
    int idx = blockIdx.x * blockDim.x + threadIdx.x;
    int ch = idx & (NCH - 1);
    int chunk = idx >> 14;
    int b = ch >> 9;
    int h = ch & 511;
    size_t m0 = (size_t)(chunk * CHUNK * B_SZ + b);
    const float* fp = U + m0 * N3 + 512 + h;
    const float* hi = hin + m0 * H_SZ + h;
    float* ho = hout + m0 * H_SZ + h;
    float c = ci[idx];
#pragma unroll 4
    for (int i = 0; i < CHUNK; i++) {
        float f  = fp[0];
        float xt = fp[-512];
        float r  = fp[512];
        float hv = hi[0];
        c = f * c + (1.0f - f) * xt;
        ho[0] = r * tanhf(c) + (1.0f - r) * hv;
        fp += (size_t)B_SZ * N3;
        hi += (size_t)B_SZ * H_SZ;
        ho += (size_t)B_SZ * H_SZ;
    }
}

// ---------------- max pool ----------------
__global__ void pool_partial(const float* __restrict__ hf, float* __restrict__ pm) {
    int idx = blockIdx.x * blockDim.x + threadIdx.x;
    int ch = idx & (NCH - 1);
    int seg = idx >> 14;
    int b = ch >> 9;
    int h = ch & 511;
    const float* p = hf + ((size_t)(seg * SEGLEN * B_SZ + b)) * H_SZ + h;
    float mx = -INFINITY;
#pragma unroll 8
    for (int i = 0; i < SEGLEN; i++) {
        mx = fmaxf(mx, p[0]);
        p += (size_t)B_SZ * H_SZ;
    }
    pm[idx] = mx;
}

__global__ void pool_reduce(const float* __restrict__ pm, float* __restrict__ pool) {
    int ch = blockIdx.x * blockDim.x + threadIdx.x;
    float mx = -INFINITY;
#pragma unroll
    for (int s = 0; s < SSEG; s++) mx = fmaxf(mx, pm[s * NCH + ch]);
    pool[ch] = tanhf(tanhf(mx));
}

// ---------------- tiny classifier ----------------
__global__ void classifier_kernel(const float* __restrict__ pool,
                                  const float* __restrict__ Wc,
                                  const float* __restrict__ bc,
                                  float* __restrict__ out) {
    int tid = threadIdx.x;
    int b = tid / C_SZ;
    int c = tid % C_SZ;
    float s = bc[c];
    const float* p = pool + b * H_SZ;
#pragma unroll 8
    for (int h = 0; h < H_SZ; h++) s += p[h] * Wc[h * C_SZ + c];
    out[b * C_SZ + c] = s;
}

// ---------------- launch ----------------
extern "C" void kernel_launch(void* const* d_in, const int* in_sizes, int n_in,
                              void* d_out, int out_size) {
    const int*   x     = (const int*)d_in[0];
    const float* embed = (const float*)d_in[1];
    const float* W     = (const float*)d_in[2]; // (L, 512, 1536)
    const float* b     = (const float*)d_in[3]; // (L, 1024)
    const float* Wc    = (const float*)d_in[4]; // (512, 10)
    const float* bc    = (const float*)d_in[5]; // (10,)
    float* out = (float*)d_out;

    float *hA, *hB, *U, *Ac, *Bc, *ci, *pm, *pool;
    __nv_bfloat16 *Ahi, *Alo, *Bhi, *Blo;
    cudaGetSymbolAddress((void**)&hA, g_hA);
    cudaGetSymbolAddress((void**)&hB, g_hB);
    cudaGetSymbolAddress((void**)&U,  g_U);
    cudaGetSymbolAddress((void**)&Ahi, g_Ahi);
    cudaGetSymbolAddress((void**)&Alo, g_Alo);
    cudaGetSymbolAddress((void**)&Bhi, g_Bhi);
    cudaGetSymbolAddress((void**)&Blo, g_Blo);
    cudaGetSymbolAddress((void**)&Ac, g_Ac);
    cudaGetSymbolAddress((void**)&Bc, g_Bc);
    cudaGetSymbolAddress((void**)&ci, g_ci);
    cudaGetSymbolAddress((void**)&pm, g_pm);
    cudaGetSymbolAddress((void**)&pool, g_pool);

    cudaFuncSetAttribute(gemm_mma_kernel, cudaFuncAttributeMaxDynamicSharedMemorySize, DYN_SMEM);

    // weight conversion (both layers at once: identity layout, 2*512*1536 elems / 4)
    convert_kernel<<<(2 * K_SZ * N3 / 4) / 256, 256>>>(W, Bhi, Blo);

    // embedding gather
    gather_kernel<<<(M_SZ * 128) / 256, 256>>>(x, embed, hA);

    dim3 gemmGrid(NTILES, MTILES); // x fastest -> 12 CTAs share one A tile via L2
    const int scanBlocks = (NCHUNK * NCH) / 256;
    const int convBlocks = ((size_t)M_SZ * K_SZ / 4) / 256;

    // layer 0: hA -> hB
    convert_kernel<<<convBlocks, 256>>>(hA, Ahi, Alo);
    gemm_mma_kernel<<<gemmGrid, 256, DYN_SMEM>>>(Ahi, Alo, Bhi, Blo, b, U);
    scan_passA<<<scanBlocks, 256>>>(U, Ac, Bc);
    scan_passB<<<NCH / 256, 256>>>(Ac, Bc, ci);
    scan_passC<<<scanBlocks, 256>>>(U, ci, hA, hB);

    // layer 1: hB -> hA
    convert_kernel<<<convBlocks, 256>>>(hB, Ahi, Alo);
    gemm_mma_kernel<<<gemmGrid, 256, DYN_SMEM>>>(Ahi, Alo, Bhi + (size_t)K_SZ * N3,
                                                 Blo + (size_t)K_SZ * N3, b + 2 * H_SZ, U);
    scan_passA<<<scanBlocks, 256>>>(U, Ac, Bc);
    scan_passB<<<NCH / 256, 256>>>(Ac, Bc, ci);
    scan_passC<<<scanBlocks, 256>>>(U, ci, hB, hA);

    // pool + classifier
    pool_partial<<<(SSEG * NCH) / 256, 256>>>(hA, pm);
    pool_reduce<<<NCH / 256, 256>>>(pm, pool);
    classifier_kernel<<<1, B_SZ * C_SZ>>>(pool, Wc, bc, out);
}

// round 4
// speedup vs baseline: 2.1122x; 1.2167x over previous
#include <cuda_runtime.h>
#include <cuda_bf16.h>
#include <math.h>
#include <stdint.h>

#define S_LEN   2048
#define B_SZ    32
#define D_SZ    512
#define H_SZ    512
#define N3      1536            // 3*H
#define M_SZ    (S_LEN * B_SZ)  // 65536
#define K_SZ    512
#define CHUNK   32
#define NCHUNK  (S_LEN / CHUNK) // 64
#define NCH     (B_SZ * H_SZ)   // 16384
#define SSEG    16
#define SEGLEN  (S_LEN / SSEG)  // 128
#define C_SZ    10

// ---------------- GEMM tiling ----------------
#define BM 128
#define BN 128
#define BK 32
#define KT_ITERS (K_SZ / BK)    // 16
#define STAGES 3
#define MTILES (M_SZ / BM)      // 512
#define NTILES (N3 / BN)        // 12

// smem pitches (bytes), padded for conflict-free ldmatrix
#define A_PITCH 80              // 32 bf16 = 64B + 16B pad
#define B_PITCH 272             // 128 bf16 = 256B + 16B pad
#define ST_A_HI 0
#define ST_A_LO (BM * A_PITCH)                 // 10240
#define ST_B_HI (2 * BM * A_PITCH)             // 20480
#define ST_B_LO (2 * BM * A_PITCH + BK * B_PITCH)      // 29184
#define ST_BYTES (2 * BM * A_PITCH + 2 * BK * B_PITCH) // 37888
#define DYN_SMEM (STAGES * ST_BYTES)           // 113664 -> 2 CTAs/SM

// ---------------- scratch (device globals: allocation-free rule) ----------------
__device__ float          g_hA[(size_t)M_SZ * H_SZ];   // 128 MB
__device__ float          g_hB[(size_t)M_SZ * H_SZ];   // 128 MB
__device__ float          g_U [(size_t)M_SZ * N3];     // 384 MB
__device__ __nv_bfloat16  g_Ahi[(size_t)M_SZ * K_SZ];  // 64 MB
__device__ __nv_bfloat16  g_Alo[(size_t)M_SZ * K_SZ];  // 64 MB
__device__ __nv_bfloat16  g_Bhi[2 * K_SZ * N3];        // 3 MB
__device__ __nv_bfloat16  g_Blo[2 * K_SZ * N3];        // 3 MB
__device__ float          g_Ac[NCHUNK * NCH];
__device__ float          g_Bc[NCHUNK * NCH];
__device__ float          g_ci[NCHUNK * NCH];
__device__ float          g_pm[SSEG * NCH];
__device__ float          g_pool[NCH];

// ---------------- PTX helpers ----------------
__device__ __forceinline__ uint32_t smem_u32(const void* p) {
    uint32_t a;
    asm("{ .reg .u64 t; cvta.to.shared.u64 t, %1; cvt.u32.u64 %0, t; }" : "=r"(a) : "l"(p));
    return a;
}

__device__ __forceinline__ void cp16(uint32_t dst, const void* src) {
    asm volatile("cp.async.cg.shared.global [%0], [%1], 16;" :: "r"(dst), "l"(src));
}
#define CP_COMMIT() asm volatile("cp.async.commit_group;" ::: "memory")
#define CP_WAIT(n)  asm volatile("cp.async.wait_group %0;" :: "n"(n) : "memory")

__device__ __forceinline__ void ldsm_x4(uint32_t& r0, uint32_t& r1, uint32_t& r2, uint32_t& r3,
                                        uint32_t addr) {
    asm volatile("ldmatrix.sync.aligned.m8n8.x4.shared.b16 {%0,%1,%2,%3}, [%4];"
                 : "=r"(r0), "=r"(r1), "=r"(r2), "=r"(r3) : "r"(addr));
}
__device__ __forceinline__ void ldsm_x4_t(uint32_t& r0, uint32_t& r1, uint32_t& r2, uint32_t& r3,
                                          uint32_t addr) {
    asm volatile("ldmatrix.sync.aligned.m8n8.x4.trans.shared.b16 {%0,%1,%2,%3}, [%4];"
                 : "=r"(r0), "=r"(r1), "=r"(r2), "=r"(r3) : "r"(addr));
}

__device__ __forceinline__ void mma_bf16(float& c0, float& c1, float& c2, float& c3,
                                         uint32_t a0, uint32_t a1, uint32_t a2, uint32_t a3,
                                         uint32_t b0, uint32_t b1) {
    asm volatile(
        "mma.sync.aligned.m16n8k16.row.col.f32.bf16.bf16.f32 "
        "{%0,%1,%2,%3}, {%4,%5,%6,%7}, {%8,%9}, {%0,%1,%2,%3};"
        : "+f"(c0), "+f"(c1), "+f"(c2), "+f"(c3)
        : "r"(a0), "r"(a1), "r"(a2), "r"(a3), "r"(b0), "r"(b1));
}

__device__ __forceinline__ float sigm(float x) { return 1.0f / (1.0f + expf(-x)); }

// ---------------- bf16 split helpers ----------------
__device__ __forceinline__ uint2 split_hi(float4 a, float4& rest) {
    __nv_bfloat16 h0 = __float2bfloat16_rn(a.x);
    __nv_bfloat16 h1 = __float2bfloat16_rn(a.y);
    __nv_bfloat16 h2 = __float2bfloat16_rn(a.z);
    __nv_bfloat16 h3 = __float2bfloat16_rn(a.w);
    rest.x = a.x - __bfloat162float(h0);
    rest.y = a.y - __bfloat162float(h1);
    rest.z = a.z - __bfloat162float(h2);
    rest.w = a.w - __bfloat162float(h3);
    __nv_bfloat162 p0 = __halves2bfloat162(h0, h1);
    __nv_bfloat162 p1 = __halves2bfloat162(h2, h3);
    uint2 r;
    r.x = *reinterpret_cast<uint32_t*>(&p0);
    r.y = *reinterpret_cast<uint32_t*>(&p1);
    return r;
}
__device__ __forceinline__ uint2 pack_bf4(float4 a) {
    __nv_bfloat162 p0 = __halves2bfloat162(__float2bfloat16_rn(a.x), __float2bfloat16_rn(a.y));
    __nv_bfloat162 p1 = __halves2bfloat162(__float2bfloat16_rn(a.z), __float2bfloat16_rn(a.w));
    uint2 r;
    r.x = *reinterpret_cast<uint32_t*>(&p0);
    r.y = *reinterpret_cast<uint32_t*>(&p1);
    return r;
}

// ---------------- embedding gather + fused bf16 split ----------------
__global__ void gather_kernel(const int* __restrict__ x,
                              const float* __restrict__ embed,
                              float* __restrict__ h,
                              __nv_bfloat16* __restrict__ hi,
                              __nv_bfloat16* __restrict__ lo) {
    size_t idx = (size_t)blockIdx.x * blockDim.x + threadIdx.x;
    int m = (int)(idx >> 7);
    int j = (int)(idx & 127);
    int row = x[m];
    float4 a = reinterpret_cast<const float4*>(embed)[(size_t)row * 128 + j];
    reinterpret_cast<float4*>(h)[idx] = a;
    float4 rest;
    uint2 hw = split_hi(a, rest);
    uint2 lw = pack_bf4(rest);
    reinterpret_cast<uint2*>(hi)[idx] = hw;
    reinterpret_cast<uint2*>(lo)[idx] = lw;
}

// ---------------- weight conversion: fp32 -> bf16 hi/lo (identity layout) ----------------
__global__ void convert_kernel(const float* __restrict__ src,
                               __nv_bfloat16* __restrict__ hi,
                               __nv_bfloat16* __restrict__ lo) {
    size_t idx = (size_t)blockIdx.x * blockDim.x + threadIdx.x;
    float4 a = reinterpret_cast<const float4*>(src)[idx];
    float4 rest;
    uint2 hw = split_hi(a, rest);
    uint2 lw = pack_bf4(rest);
    reinterpret_cast<uint2*>(hi)[idx] = hw;
    reinterpret_cast<uint2*>(lo)[idx] = lw;
}

// ---------------- bf16 HMMA GEMM: 128x128x512, 3-term split, fused gate ----------------
__global__ __launch_bounds__(256, 2) void gemm_mma_kernel(
    const __nv_bfloat16* __restrict__ Ahi, const __nv_bfloat16* __restrict__ Alo,
    const __nv_bfloat16* __restrict__ Bhi, const __nv_bfloat16* __restrict__ Blo,
    const float* __restrict__ bias,   // 1024 (f then r)
    float* __restrict__ U)
{
    extern __shared__ __align__(1024) char smem[];
    __shared__ float s_bias[BN];

    const int tid = threadIdx.x;
    const int lane = tid & 31;
    const int wid = tid >> 5;
    const int wm = wid >> 2;          // 0..1
    const int wn = wid & 3;           // 0..3
    const int ntile = blockIdx.x;
    const int mtile = blockIdx.y;
    const int n0 = ntile * BN;
    const int m0 = mtile * BM;
    const bool gate = (n0 >= 512);

    if (tid < BN) s_bias[tid] = gate ? bias[n0 - 512 + tid] : 0.0f;

    const uint32_t sbase = smem_u32(smem);
    const int c0i = tid, c1i = tid + 256;

#define LOAD_STAGE(kt, st) do {                                                    \
        uint32_t sb = sbase + (st) * ST_BYTES;                                     \
        int kk = (kt) * BK;                                                        \
        {   int am = c0i >> 2, ak = c0i & 3;                                       \
            cp16(sb + ST_A_HI + am * A_PITCH + ak * 16,                            \
                 Ahi + (size_t)(m0 + am) * K_SZ + kk + ak * 8);                    \
            cp16(sb + ST_A_LO + am * A_PITCH + ak * 16,                            \
                 Alo + (size_t)(m0 + am) * K_SZ + kk + ak * 8); }                  \
        {   int am = c1i >> 2, ak = c1i & 3;                                       \
            cp16(sb + ST_A_HI + am * A_PITCH + ak * 16,                            \
                 Ahi + (size_t)(m0 + am) * K_SZ + kk + ak * 8);                    \
            cp16(sb + ST_A_LO + am * A_PITCH + ak * 16,                            \
                 Alo + (size_t)(m0 + am) * K_SZ + kk + ak * 8); }                  \
        {   int bk = c0i >> 4, bq = c0i & 15;                                      \
            cp16(sb + ST_B_HI + bk * B_PITCH + bq * 16,                            \
                 Bhi + (size_t)(kk + bk) * N3 + n0 + bq * 8);                      \
            cp16(sb + ST_B_LO + bk * B_PITCH + bq * 16,                            \
                 Blo + (size_t)(kk + bk) * N3 + n0 + bq * 8); }                    \
        {   int bk = c1i >> 4, bq = c1i & 15;                                      \
            cp16(sb + ST_B_HI + bk * B_PITCH + bq * 16,                            \
                 Bhi + (size_t)(kk + bk) * N3 + n0 + bq * 8);                      \
            cp16(sb + ST_B_LO + bk * B_PITCH + bq * 16,                            \
                 Blo + (size_t)(kk + bk) * N3 + n0 + bq * 8); }                    \
    } while (0)

    float acc[4][4][4];
#pragma unroll
    for (int i = 0; i < 4; i++)
#pragma unroll
        for (int j = 0; j < 4; j++)
#pragma unroll
            for (int q = 0; q < 4; q++) acc[i][j][q] = 0.0f;

    // prologue: fill all 3 stages
    LOAD_STAGE(0, 0); CP_COMMIT();
    LOAD_STAGE(1, 1); CP_COMMIT();
    LOAD_STAGE(2, 2); CP_COMMIT();

    const int lrow = lane & 15;
    const int lcol8 = (lane >> 4) * 8;

    for (int kt = 0; kt < KT_ITERS; kt++) {
        const int st = kt % STAGES;
        CP_WAIT(2);
        __syncthreads();

        const uint32_t sb = sbase + st * ST_BYTES;
        const uint32_t sAhi = sb + ST_A_HI + (wm * 64 + lrow) * A_PITCH;
        const uint32_t sAlo = sb + ST_A_LO + (wm * 64 + lrow) * A_PITCH;
        const uint32_t sBhi = sb + ST_B_HI + lrow * B_PITCH + (wn * 32 + lcol8) * 2;
        const uint32_t sBlo = sb + ST_B_LO + lrow * B_PITCH + (wn * 32 + lcol8) * 2;

#pragma unroll
        for (int k16 = 0; k16 < 2; k16++) {
            uint32_t bh[2][4], bl[2][4];
#pragma unroll
            for (int nj = 0; nj < 2; nj++) {
                uint32_t bo = k16 * 16 * B_PITCH + nj * 16 * 2;
                ldsm_x4_t(bh[nj][0], bh[nj][1], bh[nj][2], bh[nj][3], sBhi + bo);
                ldsm_x4_t(bl[nj][0], bl[nj][1], bl[nj][2], bl[nj][3], sBlo + bo);
            }
            // per-mi A fragment load keeps the live register set small (fits 128-reg cap)
#pragma unroll
            for (int mi = 0; mi < 4; mi++) {
                uint32_t ah[4], al[4];
                uint32_t ao = mi * 16 * A_PITCH + (k16 * 16 + lcol8) * 2;
                ldsm_x4(ah[0], ah[1], ah[2], ah[3], sAhi + ao);
                ldsm_x4(al[0], al[1], al[2], al[3], sAlo + ao);
#pragma unroll
                for (int n8 = 0; n8 < 4; n8++) {
                    float* c = acc[mi][n8];
                    uint32_t b0h = bh[n8 >> 1][(n8 & 1) * 2], b1h = bh[n8 >> 1][(n8 & 1) * 2 + 1];
                    uint32_t b0l = bl[n8 >> 1][(n8 & 1) * 2], b1l = bl[n8 >> 1][(n8 & 1) * 2 + 1];
                    mma_bf16(c[0], c[1], c[2], c[3], ah[0], ah[1], ah[2], ah[3], b0h, b1h);
                    mma_bf16(c[0], c[1], c[2], c[3], ah[0], ah[1], ah[2], ah[3], b0l, b1l);
                    mma_bf16(c[0], c[1], c[2], c[3], al[0], al[1], al[2], al[3], b0h, b1h);
                }
            }
        }
        __syncthreads();    // protect slot st before refill

        if (kt + STAGES < KT_ITERS) LOAD_STAGE(kt + STAGES, st);
        CP_COMMIT();        // unconditional: keeps wait_group counting aligned
    }

    // ---- epilogue: bias + sigmoid on gate tiles, float2 stores ----
    const int g = lane >> 2;
    const int tig = lane & 3;
#pragma unroll
    for (int mi = 0; mi < 4; mi++) {
        int row = m0 + wm * 64 + mi * 16 + g;
#pragma unroll
        for (int n8 = 0; n8 < 4; n8++) {
            int coll = wn * 32 + n8 * 8 + tig * 2;
            float v0 = acc[mi][n8][0], v1 = acc[mi][n8][1];
            float v2 = acc[mi][n8][2], v3 = acc[mi][n8][3];
            if (gate) {
                float b0 = s_bias[coll], b1 = s_bias[coll + 1];
                v0 = sigm(v0 + b0); v1 = sigm(v1 + b1);
                v2 = sigm(v2 + b0); v3 = sigm(v3 + b1);
            }
            float2 p0 = {v0, v1}, p1 = {v2, v3};
            *reinterpret_cast<float2*>(&U[(size_t)row * N3 + n0 + coll]) = p0;
            *reinterpret_cast<float2*>(&U[(size_t)(row + 8) * N3 + n0 + coll]) = p1;
        }
    }
#undef LOAD_STAGE
}

// ---------------- scan pass A: per-chunk affine composition ----------------
__global__ void scan_passA(const float* __restrict__ U,
                           float* __restrict__ Ac, float* __restrict__ Bc) {
    int idx = blockIdx.x * blockDim.x + threadIdx.x;
    int ch = idx & (NCH - 1);
    int chunk = idx >> 14;
    int b = ch >> 9;
    int h = ch & 511;
    const float* fp = U + ((size_t)(chunk * CHUNK * B_SZ + b)) * N3 + 512 + h;
    float Aa = 1.0f, Bb = 0.0f;
#pragma unroll 8
    for (int i = 0; i < CHUNK; i++) {
        float f  = fp[0];
        float xt = fp[-512];
        Bb = f * Bb + (1.0f - f) * xt;
        Aa *= f;
        fp += (size_t)B_SZ * N3;
    }
    Ac[idx] = Aa;
    Bc[idx] = Bb;
}

// ---------------- scan pass B: prefix over chunks ----------------
__global__ void scan_passB(const float* __restrict__ Ac,
                           const float* __restrict__ Bc,
                           float* __restrict__ ci) {
    int ch = blockIdx.x * blockDim.x + threadIdx.x;
    float c = 0.0f;
#pragma unroll 8
    for (int k = 0; k < NCHUNK; k++) {
        ci[k * NCH + ch] = c;
        c = Ac[k * NCH + ch] * c + Bc[k * NCH + ch];
    }
}

// ---------------- scan pass C: rescan + highway output + fused bf16 split ----------------
__global__ void scan_passC(const float* __restrict__ U,
                           const float* __restrict__ ci,
                           const float* __restrict__ hin,
                           float* __restrict__ hout,
                           __nv_bfloat16* __restrict__ hi_out,
                           __nv_bfloat16* __restrict__ lo_out,
                           int emit) {
    int idx = blockIdx.x * blockDim.x + threadIdx.x;
    int ch = idx & (NCH - 1);
    int chunk = idx >> 14;
    int b = ch >> 9;
    int h = ch & 511;
    size_t m0 = (size_t)(chunk * CHUNK * B_SZ + b);
    const float* fp = U + m0 * N3 + 512 + h;
    size_t hoff = m0 * H_SZ + h;
    float c = ci[idx];
#pragma unroll 4
    for (int i = 0; i < CHUNK; i++) {
        float f  = fp[0];
        float xt = fp[-512];
        float r  = fp[512];
        float hv = hin[hoff];
        c = f * c + (1.0f - f) * xt;
        float o = r * tanhf(c) + (1.0f - r) * hv;
        hout[hoff] = o;
        if (emit) {
            __nv_bfloat16 oh = __float2bfloat16_rn(o);
            hi_out[hoff] = oh;
            lo_out[hoff] = __float2bfloat16_rn(o - __bfloat162float(oh));
        }
        fp += (size_t)B_SZ * N3;
        hoff += (size_t)B_SZ * H_SZ;
    }
}

// ---------------- max pool ----------------
__global__ void pool_partial(const float* __restrict__ hf, float* __restrict__ pm) {
    int idx = blockIdx.x * blockDim.x + threadIdx.x;
    int ch = idx & (NCH - 1);
    int seg = idx >> 14;
    int b = ch >> 9;
    int h = ch & 511;
    const float* p = hf + ((size_t)(seg * SEGLEN * B_SZ + b)) * H_SZ + h;
    float mx = -INFINITY;
#pragma unroll 8
    for (int i = 0; i < SEGLEN; i++) {
        mx = fmaxf(mx, p[0]);
        p += (size_t)B_SZ * H_SZ;
    }
    pm[idx] = mx;
}

__global__ void pool_reduce(const float* __restrict__ pm, float* __restrict__ pool) {
    int ch = blockIdx.x * blockDim.x + threadIdx.x;
    float mx = -INFINITY;
#pragma unroll
    for (int s = 0; s < SSEG; s++) mx = fmaxf(mx, pm[s * NCH + ch]);
    pool[ch] = tanhf(tanhf(mx));
}

// ---------------- tiny classifier ----------------
__global__ void classifier_kernel(const float* __restrict__ pool,
                                  const float* __restrict__ Wc,
                                  const float* __restrict__ bc,
                                  float* __restrict__ out) {
    int tid = threadIdx.x;
    int b = tid / C_SZ;
    int c = tid % C_SZ;
    float s = bc[c];
    const float* p = pool + b * H_SZ;
#pragma unroll 8
    for (int h = 0; h < H_SZ; h++) s += p[h] * Wc[h * C_SZ + c];
    out[b * C_SZ + c] = s;
}

// ---------------- launch ----------------
extern "C" void kernel_launch(void* const* d_in, const int* in_sizes, int n_in,
                              void* d_out, int out_size) {
    const int*   x     = (const int*)d_in[0];
    const float* embed = (const float*)d_in[1];
    const float* W     = (const float*)d_in[2]; // (L, 512, 1536)
    const float* b     = (const float*)d_in[3]; // (L, 1024)
    const float* Wc    = (const float*)d_in[4]; // (512, 10)
    const float* bc    = (const float*)d_in[5]; // (10,)
    float* out = (float*)d_out;

    float *hA, *hB, *U, *Ac, *Bc, *ci, *pm, *pool;
    __nv_bfloat16 *Ahi, *Alo, *Bhi, *Blo;
    cudaGetSymbolAddress((void**)&hA, g_hA);
    cudaGetSymbolAddress((void**)&hB, g_hB);
    cudaGetSymbolAddress((void**)&U,  g_U);
    cudaGetSymbolAddress((void**)&Ahi, g_Ahi);
    cudaGetSymbolAddress((void**)&Alo, g_Alo);
    cudaGetSymbolAddress((void**)&Bhi, g_Bhi);
    cudaGetSymbolAddress((void**)&Blo, g_Blo);
    cudaGetSymbolAddress((void**)&Ac, g_Ac);
    cudaGetSymbolAddress((void**)&Bc, g_Bc);
    cudaGetSymbolAddress((void**)&ci, g_ci);
    cudaGetSymbolAddress((void**)&pm, g_pm);
    cudaGetSymbolAddress((void**)&pool, g_pool);

    cudaFuncSetAttribute(gemm_mma_kernel, cudaFuncAttributeMaxDynamicSharedMemorySize, DYN_SMEM);

    // weight conversion (both layers at once)
    convert_kernel<<<(2 * K_SZ * N3 / 4) / 256, 256>>>(W, Bhi, Blo);

    // embedding gather (emits fp32 h + bf16 hi/lo for layer-0 GEMM)
    gather_kernel<<<(M_SZ * 128) / 256, 256>>>(x, embed, hA, Ahi, Alo);

    dim3 gemmGrid(NTILES, MTILES); // x fastest -> 12 CTAs share one A tile via L2
    const int scanBlocks = (NCHUNK * NCH) / 256;

    // layer 0: hA -> hB (passC emits hi/lo for layer-1 GEMM)
    gemm_mma_kernel<<<gemmGrid, 256, DYN_SMEM>>>(Ahi, Alo, Bhi, Blo, b, U);
    scan_passA<<<scanBlocks, 256>>>(U, Ac, Bc);
    scan_passB<<<NCH / 256, 256>>>(Ac, Bc, ci);
    scan_passC<<<scanBlocks, 256>>>(U, ci, hA, hB, Ahi, Alo, 1);

    // layer 1: hB -> hA
    gemm_mma_kernel<<<gemmGrid, 256, DYN_SMEM>>>(Ahi, Alo, Bhi + (size_t)K_SZ * N3,
                                                 Blo + (size_t)K_SZ * N3, b + 2 * H_SZ, U);
    scan_passA<<<scanBlocks, 256>>>(U, Ac, Bc);
    scan_passB<<<NCH / 256, 256>>>(Ac, Bc, ci);
    scan_passC<<<scanBlocks, 256>>>(U, ci, hB, hA, Ahi, Alo, 0);

    // pool + classifier
    pool_partial<<<(SSEG * NCH) / 256, 256>>>(hA, pm);
    pool_reduce<<<NCH / 256, 256>>>(pm, pool);
    classifier_kernel<<<1, B_SZ * C_SZ>>>(pool, Wc, bc, out);
}

// round 5
// speedup vs baseline: 2.5496x; 1.2071x over previous
#include <cuda_runtime.h>
#include <cuda_bf16.h>
#include <math.h>
#include <stdint.h>

#define S_LEN   2048
#define B_SZ    32
#define D_SZ    512
#define H_SZ    512
#define N3      1536            // 3*H
#define M_SZ    (S_LEN * B_SZ)  // 65536
#define K_SZ    512
#define CHUNK   32
#define NCHUNK  (S_LEN / CHUNK) // 64
#define NCH     (B_SZ * H_SZ)   // 16384
#define C_SZ    10

// ---------------- GEMM tiling ----------------
#define BM 128
#define BN 128
#define BK 32
#define KT_ITERS (K_SZ / BK)    // 16
#define STAGES 3
#define MTILES (M_SZ / BM)      // 512
#define NTILES (N3 / BN)        // 12

// smem pitches (bytes), padded for conflict-free ldmatrix
#define A_PITCH 80              // 32 bf16 = 64B + 16B pad
#define B_PITCH 272             // 128 bf16 = 256B + 16B pad
#define ST_A_HI 0
#define ST_A_LO (BM * A_PITCH)                 // 10240
#define ST_B_HI (2 * BM * A_PITCH)             // 20480
#define ST_B_LO (2 * BM * A_PITCH + BK * B_PITCH)      // 29184
#define ST_BYTES (2 * BM * A_PITCH + 2 * BK * B_PITCH) // 37888
#define DYN_SMEM (STAGES * ST_BYTES)           // 113664 -> 2 CTAs/SM

// ---------------- scratch (device globals: allocation-free rule) ----------------
__device__ float          g_hA[(size_t)M_SZ * H_SZ];   // 128 MB
__device__ float          g_hB[(size_t)M_SZ * H_SZ];   // 128 MB
__device__ float          g_U [(size_t)M_SZ * N3];     // 384 MB
__device__ __nv_bfloat16  g_Ahi[(size_t)M_SZ * K_SZ];  // 64 MB
__device__ __nv_bfloat16  g_Alo[(size_t)M_SZ * K_SZ];  // 64 MB
__device__ __nv_bfloat16  g_Bhi[2 * K_SZ * N3];        // 3 MB
__device__ __nv_bfloat16  g_Blo[2 * K_SZ * N3];        // 3 MB
__device__ float          g_Ac[NCHUNK * NCH];
__device__ float          g_Bc[NCHUNK * NCH];
__device__ float          g_ci[NCHUNK * NCH];
__device__ float          g_pm[NCHUNK * NCH];          // 4 MB (chunk-level max)
__device__ float          g_pool[NCH];

// ---------------- PTX helpers ----------------
__device__ __forceinline__ uint32_t smem_u32(const void* p) {
    uint32_t a;
    asm("{ .reg .u64 t; cvta.to.shared.u64 t, %1; cvt.u32.u64 %0, t; }" : "=r"(a) : "l"(p));
    return a;
}

__device__ __forceinline__ void cp16(uint32_t dst, const void* src) {
    asm volatile("cp.async.cg.shared.global [%0], [%1], 16;" :: "r"(dst), "l"(src));
}
#define CP_COMMIT() asm volatile("cp.async.commit_group;" ::: "memory")
#define CP_WAIT(n)  asm volatile("cp.async.wait_group %0;" :: "n"(n) : "memory")

__device__ __forceinline__ void ldsm_x4(uint32_t& r0, uint32_t& r1, uint32_t& r2, uint32_t& r3,
                                        uint32_t addr) {
    asm volatile("ldmatrix.sync.aligned.m8n8.x4.shared.b16 {%0,%1,%2,%3}, [%4];"
                 : "=r"(r0), "=r"(r1), "=r"(r2), "=r"(r3) : "r"(addr));
}
__device__ __forceinline__ void ldsm_x4_t(uint32_t& r0, uint32_t& r1, uint32_t& r2, uint32_t& r3,
                                          uint32_t addr) {
    asm volatile("ldmatrix.sync.aligned.m8n8.x4.trans.shared.b16 {%0,%1,%2,%3}, [%4];"
                 : "=r"(r0), "=r"(r1), "=r"(r2), "=r"(r3) : "r"(addr));
}

__device__ __forceinline__ void mma_bf16(float& c0, float& c1, float& c2, float& c3,
                                         uint32_t a0, uint32_t a1, uint32_t a2, uint32_t a3,
                                         uint32_t b0, uint32_t b1) {
    asm volatile(
        "mma.sync.aligned.m16n8k16.row.col.f32.bf16.bf16.f32 "
        "{%0,%1,%2,%3}, {%4,%5,%6,%7}, {%8,%9}, {%0,%1,%2,%3};"
        : "+f"(c0), "+f"(c1), "+f"(c2), "+f"(c3)
        : "r"(a0), "r"(a1), "r"(a2), "r"(a3), "r"(b0), "r"(b1));
}

__device__ __forceinline__ float sigm(float x) { return 1.0f / (1.0f + expf(-x)); }

// ---------------- bf16 split helpers ----------------
__device__ __forceinline__ uint2 split_hi(float4 a, float4& rest) {
    __nv_bfloat16 h0 = __float2bfloat16_rn(a.x);
    __nv_bfloat16 h1 = __float2bfloat16_rn(a.y);
    __nv_bfloat16 h2 = __float2bfloat16_rn(a.z);
    __nv_bfloat16 h3 = __float2bfloat16_rn(a.w);
    rest.x = a.x - __bfloat162float(h0);
    rest.y = a.y - __bfloat162float(h1);
    rest.z = a.z - __bfloat162float(h2);
    rest.w = a.w - __bfloat162float(h3);
    __nv_bfloat162 p0 = __halves2bfloat162(h0, h1);
    __nv_bfloat162 p1 = __halves2bfloat162(h2, h3);
    uint2 r;
    r.x = *reinterpret_cast<uint32_t*>(&p0);
    r.y = *reinterpret_cast<uint32_t*>(&p1);
    return r;
}
__device__ __forceinline__ uint2 pack_bf4(float4 a) {
    __nv_bfloat162 p0 = __halves2bfloat162(__float2bfloat16_rn(a.x), __float2bfloat16_rn(a.y));
    __nv_bfloat162 p1 = __halves2bfloat162(__float2bfloat16_rn(a.z), __float2bfloat16_rn(a.w));
    uint2 r;
    r.x = *reinterpret_cast<uint32_t*>(&p0);
    r.y = *reinterpret_cast<uint32_t*>(&p1);
    return r;
}

// ---------------- embedding gather + fused bf16 split ----------------
__global__ void gather_kernel(const int* __restrict__ x,
                              const float* __restrict__ embed,
                              float* __restrict__ h,
                              __nv_bfloat16* __restrict__ hi,
                              __nv_bfloat16* __restrict__ lo) {
    size_t idx = (size_t)blockIdx.x * blockDim.x + threadIdx.x;
    int m = (int)(idx >> 7);
    int j = (int)(idx & 127);
    int row = x[m];
    float4 a = reinterpret_cast<const float4*>(embed)[(size_t)row * 128 + j];
    reinterpret_cast<float4*>(h)[idx] = a;
    float4 rest;
    uint2 hw = split_hi(a, rest);
    uint2 lw = pack_bf4(rest);
    reinterpret_cast<uint2*>(hi)[idx] = hw;
    reinterpret_cast<uint2*>(lo)[idx] = lw;
}

// ---------------- weight conversion ----------------
__global__ void convert_kernel(const float* __restrict__ src,
                               __nv_bfloat16* __restrict__ hi,
                               __nv_bfloat16* __restrict__ lo) {
    size_t idx = (size_t)blockIdx.x * blockDim.x + threadIdx.x;
    float4 a = reinterpret_cast<const float4*>(src)[idx];
    float4 rest;
    uint2 hw = split_hi(a, rest);
    uint2 lw = pack_bf4(rest);
    reinterpret_cast<uint2*>(hi)[idx] = hw;
    reinterpret_cast<uint2*>(lo)[idx] = lw;
}

// ---------------- GEMM mainloop body (TERMS = 3 for xt cols, 2 for gate cols) ----------------
template<int TERMS>
__device__ __forceinline__ void gemm_body(
    const __nv_bfloat16* __restrict__ Ahi, const __nv_bfloat16* __restrict__ Alo,
    const __nv_bfloat16* __restrict__ Bhi, const __nv_bfloat16* __restrict__ Blo,
    int m0, int n0, uint32_t sbase, int tid, float acc[4][4][4])
{
    const int lane = tid & 31;
    const int wid = tid >> 5;
    const int wm = wid >> 2;
    const int wn = wid & 3;
    const int lrow = lane & 15;
    const int lcol8 = (lane >> 4) * 8;

    auto load_stage = [&](int kt, int st) {
        uint32_t sb = sbase + st * ST_BYTES;
        int kk = kt * BK;
#pragma unroll
        for (int c = 0; c < 2; c++) {
            int ci = tid + c * 256;
            int am = ci >> 2, ak = ci & 3;
            cp16(sb + ST_A_HI + am * A_PITCH + ak * 16,
                 Ahi + (size_t)(m0 + am) * K_SZ + kk + ak * 8);
            if (TERMS == 3)
                cp16(sb + ST_A_LO + am * A_PITCH + ak * 16,
                     Alo + (size_t)(m0 + am) * K_SZ + kk + ak * 8);
            int bk = ci >> 4, bq = ci & 15;
            cp16(sb + ST_B_HI + bk * B_PITCH + bq * 16,
                 Bhi + (size_t)(kk + bk) * N3 + n0 + bq * 8);
            cp16(sb + ST_B_LO + bk * B_PITCH + bq * 16,
                 Blo + (size_t)(kk + bk) * N3 + n0 + bq * 8);
        }
    };

    // prologue: stages 0,1
    load_stage(0, 0); CP_COMMIT();
    load_stage(1, 1); CP_COMMIT();

    for (int kt = 0; kt < KT_ITERS; kt++) {
        const int st = kt % STAGES;
        CP_WAIT(1);
        __syncthreads();   // single barrier: stage kt readable by all; slot (kt+2)%3 drained

        if (kt + 2 < KT_ITERS) load_stage(kt + 2, (kt + 2) % STAGES);
        CP_COMMIT();       // unconditional: keeps wait_group counting aligned

        const uint32_t sb = sbase + st * ST_BYTES;
        const uint32_t sAhi = sb + ST_A_HI + (wm * 64 + lrow) * A_PITCH;
        const uint32_t sAlo = sb + ST_A_LO + (wm * 64 + lrow) * A_PITCH;
        const uint32_t sBhi = sb + ST_B_HI + lrow * B_PITCH + (wn * 32 + lcol8) * 2;
        const uint32_t sBlo = sb + ST_B_LO + lrow * B_PITCH + (wn * 32 + lcol8) * 2;

#pragma unroll
        for (int k16 = 0; k16 < 2; k16++) {
            uint32_t bh[2][4], bl[2][4];
#pragma unroll
            for (int nj = 0; nj < 2; nj++) {
                uint32_t bo = k16 * 16 * B_PITCH + nj * 16 * 2;
                ldsm_x4_t(bh[nj][0], bh[nj][1], bh[nj][2], bh[nj][3], sBhi + bo);
                ldsm_x4_t(bl[nj][0], bl[nj][1], bl[nj][2], bl[nj][3], sBlo + bo);
            }
#pragma unroll
            for (int mi = 0; mi < 4; mi++) {
                uint32_t ah[4], al[4];
                uint32_t ao = mi * 16 * A_PITCH + (k16 * 16 + lcol8) * 2;
                ldsm_x4(ah[0], ah[1], ah[2], ah[3], sAhi + ao);
                if (TERMS == 3) ldsm_x4(al[0], al[1], al[2], al[3], sAlo + ao);
#pragma unroll
                for (int n8 = 0; n8 < 4; n8++) {
                    float* c = acc[mi][n8];
                    uint32_t b0h = bh[n8 >> 1][(n8 & 1) * 2], b1h = bh[n8 >> 1][(n8 & 1) * 2 + 1];
                    uint32_t b0l = bl[n8 >> 1][(n8 & 1) * 2], b1l = bl[n8 >> 1][(n8 & 1) * 2 + 1];
                    mma_bf16(c[0], c[1], c[2], c[3], ah[0], ah[1], ah[2], ah[3], b0h, b1h);
                    mma_bf16(c[0], c[1], c[2], c[3], ah[0], ah[1], ah[2], ah[3], b0l, b1l);
                    if (TERMS == 3)
                        mma_bf16(c[0], c[1], c[2], c[3], al[0], al[1], al[2], al[3], b0h, b1h);
                }
            }
        }
    }
}

// ---------------- bf16 HMMA GEMM: 128x128x512, mixed-term split, fused gate ----------------
__global__ __launch_bounds__(256, 2) void gemm_mma_kernel(
    const __nv_bfloat16* __restrict__ Ahi, const __nv_bfloat16* __restrict__ Alo,
    const __nv_bfloat16* __restrict__ Bhi, const __nv_bfloat16* __restrict__ Blo,
    const float* __restrict__ bias,   // 1024 (f then r)
    float* __restrict__ U)
{
    extern __shared__ __align__(1024) char smem[];
    __shared__ float s_bias[BN];

    const int tid = threadIdx.x;
    const int lane = tid & 31;
    const int wid = tid >> 5;
    const int wm = wid >> 2;
    const int wn = wid & 3;
    const int ntile = blockIdx.x;
    const int mtile = blockIdx.y;
    const int n0 = ntile * BN;
    const int m0 = mtile * BM;
    const bool gate = (n0 >= 512);

    if (tid < BN) s_bias[tid] = gate ? bias[n0 - 512 + tid] : 0.0f;

    const uint32_t sbase = smem_u32(smem);

    float acc[4][4][4];
#pragma unroll
    for (int i = 0; i < 4; i++)
#pragma unroll
        for (int j = 0; j < 4; j++)
#pragma unroll
            for (int q = 0; q < 4; q++) acc[i][j][q] = 0.0f;

    if (!gate) gemm_body<3>(Ahi, Alo, Bhi, Blo, m0, n0, sbase, tid, acc);
    else       gemm_body<2>(Ahi, Alo, Bhi, Blo, m0, n0, sbase, tid, acc);

    // ---- epilogue: bias + sigmoid on gate tiles, float2 stores ----
    const int g = lane >> 2;
    const int tig = lane & 3;
#pragma unroll
    for (int mi = 0; mi < 4; mi++) {
        int row = m0 + wm * 64 + mi * 16 + g;
#pragma unroll
        for (int n8 = 0; n8 < 4; n8++) {
            int coll = wn * 32 + n8 * 8 + tig * 2;
            float v0 = acc[mi][n8][0], v1 = acc[mi][n8][1];
            float v2 = acc[mi][n8][2], v3 = acc[mi][n8][3];
            if (gate) {
                float b0 = s_bias[coll], b1 = s_bias[coll + 1];
                v0 = sigm(v0 + b0); v1 = sigm(v1 + b1);
                v2 = sigm(v2 + b0); v3 = sigm(v3 + b1);
            }
            float2 p0 = {v0, v1}, p1 = {v2, v3};
            *reinterpret_cast<float2*>(&U[(size_t)row * N3 + n0 + coll]) = p0;
            *reinterpret_cast<float2*>(&U[(size_t)(row + 8) * N3 + n0 + coll]) = p1;
        }
    }
}

// ---------------- scan pass A: per-chunk affine composition ----------------
__global__ void scan_passA(const float* __restrict__ U,
                           float* __restrict__ Ac, float* __restrict__ Bc) {
    int idx = blockIdx.x * blockDim.x + threadIdx.x;
    int ch = idx & (NCH - 1);
    int chunk = idx >> 14;
    int b = ch >> 9;
    int h = ch & 511;
    const float* fp = U + ((size_t)(chunk * CHUNK * B_SZ + b)) * N3 + 512 + h;
    float Aa = 1.0f, Bb = 0.0f;
#pragma unroll 8
    for (int i = 0; i < CHUNK; i++) {
        float f  = fp[0];
        float xt = fp[-512];
        Bb = f * Bb + (1.0f - f) * xt;
        Aa *= f;
        fp += (size_t)B_SZ * N3;
    }
    Ac[idx] = Aa;
    Bc[idx] = Bb;
}

// ---------------- scan pass B: prefix over chunks ----------------
__global__ void scan_passB(const float* __restrict__ Ac,
                           const float* __restrict__ Bc,
                           float* __restrict__ ci) {
    int ch = blockIdx.x * blockDim.x + threadIdx.x;
    float c = 0.0f;
#pragma unroll 8
    for (int k = 0; k < NCHUNK; k++) {
        ci[k * NCH + ch] = c;
        c = Ac[k * NCH + ch] * c + Bc[k * NCH + ch];
    }
}

// ---------------- scan pass C: rescan + highway output ----------------
// mode 0: write hout + bf16 hi/lo split (feeds next layer GEMM)
// mode 1: final layer -> emit per-chunk max only (no hout store)
__global__ void scan_passC(const float* __restrict__ U,
                           const float* __restrict__ ci,
                           const float* __restrict__ hin,
                           float* __restrict__ hout,
                           __nv_bfloat16* __restrict__ hi_out,
                           __nv_bfloat16* __restrict__ lo_out,
                           float* __restrict__ pm,
                           int mode) {
    int idx = blockIdx.x * blockDim.x + threadIdx.x;
    int ch = idx & (NCH - 1);
    int chunk = idx >> 14;
    int b = ch >> 9;
    int h = ch & 511;
    size_t m0 = (size_t)(chunk * CHUNK * B_SZ + b);
    const float* fp = U + m0 * N3 + 512 + h;
    size_t hoff = m0 * H_SZ + h;
    float c = ci[idx];
    float mx = -INFINITY;
#pragma unroll 4
    for (int i = 0; i < CHUNK; i++) {
        float f  = fp[0];
        float xt = fp[-512];
        float r  = fp[512];
        float hv = hin[hoff];
        c = f * c + (1.0f - f) * xt;
        float o = r * tanhf(c) + (1.0f - r) * hv;
        if (mode == 0) {
            hout[hoff] = o;
            __nv_bfloat16 oh = __float2bfloat16_rn(o);
            hi_out[hoff] = oh;
            lo_out[hoff] = __float2bfloat16_rn(o - __bfloat162float(oh));
        } else {
            mx = fmaxf(mx, o);
        }
        fp += (size_t)B_SZ * N3;
        hoff += (size_t)B_SZ * H_SZ;
    }
    if (mode == 1) pm[idx] = mx;
}

// ---------------- pool reduce over chunks (tanh monotonic: tanh after max) ----------------
__global__ void pool_reduce(const float* __restrict__ pm, float* __restrict__ pool) {
    int ch = blockIdx.x * blockDim.x + threadIdx.x;
    float mx = -INFINITY;
#pragma unroll 8
    for (int s = 0; s < NCHUNK; s++) mx = fmaxf(mx, pm[s * NCH + ch]);
    pool[ch] = tanhf(tanhf(mx));
}

// ---------------- tiny classifier ----------------
__global__ void classifier_kernel(const float* __restrict__ pool,
                                  const float* __restrict__ Wc,
                                  const float* __restrict__ bc,
                                  float* __restrict__ out) {
    int tid = threadIdx.x;
    int b = tid / C_SZ;
    int c = tid % C_SZ;
    float s = bc[c];
    const float* p = pool + b * H_SZ;
#pragma unroll 8
    for (int h = 0; h < H_SZ; h++) s += p[h] * Wc[h * C_SZ + c];
    out[b * C_SZ + c] = s;
}

// ---------------- launch ----------------
extern "C" void kernel_launch(void* const* d_in, const int* in_sizes, int n_in,
                              void* d_out, int out_size) {
    const int*   x     = (const int*)d_in[0];
    const float* embed = (const float*)d_in[1];
    const float* W     = (const float*)d_in[2]; // (L, 512, 1536)
    const float* b     = (const float*)d_in[3]; // (L, 1024)
    const float* Wc    = (const float*)d_in[4]; // (512, 10)
    const float* bc    = (const float*)d_in[5]; // (10,)
    float* out = (float*)d_out;

    float *hA, *hB, *U, *Ac, *Bc, *ci, *pm, *pool;
    __nv_bfloat16 *Ahi, *Alo, *Bhi, *Blo;
    cudaGetSymbolAddress((void**)&hA, g_hA);
    cudaGetSymbolAddress((void**)&hB, g_hB);
    cudaGetSymbolAddress((void**)&U,  g_U);
    cudaGetSymbolAddress((void**)&Ahi, g_Ahi);
    cudaGetSymbolAddress((void**)&Alo, g_Alo);
    cudaGetSymbolAddress((void**)&Bhi, g_Bhi);
    cudaGetSymbolAddress((void**)&Blo, g_Blo);
    cudaGetSymbolAddress((void**)&Ac, g_Ac);
    cudaGetSymbolAddress((void**)&Bc, g_Bc);
    cudaGetSymbolAddress((void**)&ci, g_ci);
    cudaGetSymbolAddress((void**)&pm, g_pm);
    cudaGetSymbolAddress((void**)&pool, g_pool);

    cudaFuncSetAttribute(gemm_mma_kernel, cudaFuncAttributeMaxDynamicSharedMemorySize, DYN_SMEM);

    // weight conversion (both layers at once)
    convert_kernel<<<(2 * K_SZ * N3 / 4) / 256, 256>>>(W, Bhi, Blo);

    // embedding gather (emits fp32 h + bf16 hi/lo for layer-0 GEMM)
    gather_kernel<<<(M_SZ * 128) / 256, 256>>>(x, embed, hA, Ahi, Alo);

    dim3 gemmGrid(NTILES, MTILES); // x fastest -> 12 CTAs share one A tile via L2
    const int scanBlocks = (NCHUNK * NCH) / 256;

    // layer 0: hA -> hB (passC emits hi/lo for layer-1 GEMM)
    gemm_mma_kernel<<<gemmGrid, 256, DYN_SMEM>>>(Ahi, Alo, Bhi, Blo, b, U);
    scan_passA<<<scanBlocks, 256>>>(U, Ac, Bc);
    scan_passB<<<NCH / 256, 256>>>(Ac, Bc, ci);
    scan_passC<<<scanBlocks, 256>>>(U, ci, hA, hB, Ahi, Alo, pm, 0);

    // layer 1: hB -> (pooled chunk maxima)
    gemm_mma_kernel<<<gemmGrid, 256, DYN_SMEM>>>(Ahi, Alo, Bhi + (size_t)K_SZ * N3,
                                                 Blo + (size_t)K_SZ * N3, b + 2 * H_SZ, U);
    scan_passA<<<scanBlocks, 256>>>(U, Ac, Bc);
    scan_passB<<<NCH / 256, 256>>>(Ac, Bc, ci);
    scan_passC<<<scanBlocks, 256>>>(U, ci, hB, hA, Ahi, Alo, pm, 1);

    // pool + classifier
    pool_reduce<<<NCH / 256, 256>>>(pm, pool);
    classifier_kernel<<<1, B_SZ * C_SZ>>>(pool, Wc, bc, out);
}

// round 6
// speedup vs baseline: 3.4275x; 1.3443x over previous
#include <cuda_runtime.h>
#include <cuda_fp16.h>
#include <math.h>
#include <stdint.h>

#define S_LEN   2048
#define B_SZ    32
#define D_SZ    512
#define H_SZ    512
#define N3      1536            // 3*H
#define M_SZ    (S_LEN * B_SZ)  // 65536
#define K_SZ    512
#define CHUNK   32
#define NCHUNK  (S_LEN / CHUNK) // 64
#define NCH     (B_SZ * H_SZ)   // 16384
#define C_SZ    10

// ---------------- GEMM tiling ----------------
#define BM 128
#define BN 128
#define BK 32
#define KT_ITERS (K_SZ / BK)    // 16
#define STAGES 4
#define MTILES (M_SZ / BM)      // 512
#define NTILES (N3 / BN)        // 12

// smem pitches (bytes), padded for conflict-free ldmatrix
#define A_PITCH 80              // 32 fp16 = 64B + 16B pad
#define B_PITCH 272             // 128 fp16 = 256B + 16B pad
#define ST_A    0
#define ST_B_HI (BM * A_PITCH)                     // 10240
#define ST_B_LO (BM * A_PITCH + BK * B_PITCH)      // 18944
#define ST_BYTES (BM * A_PITCH + 2 * BK * B_PITCH) // 27648
#define DYN_SMEM (STAGES * ST_BYTES)               // 110592 -> 2 CTAs/SM

// ---------------- scratch (device globals: allocation-free rule) ----------------
__device__ float   g_hA[(size_t)M_SZ * H_SZ];   // 128 MB
__device__ float   g_hB[(size_t)M_SZ * H_SZ];   // 128 MB
__device__ float   g_U [(size_t)M_SZ * N3];     // 384 MB
__device__ __half  g_Ah[(size_t)M_SZ * K_SZ];   // 64 MB  (single fp16 A)
__device__ __half  g_Bhi[2 * K_SZ * N3];        // 3 MB
__device__ __half  g_Blo[2 * K_SZ * N3];        // 3 MB
__device__ float   g_Ac[NCHUNK * NCH];
__device__ float   g_Bc[NCHUNK * NCH];
__device__ float   g_ci[NCHUNK * NCH];
__device__ float   g_pm[NCHUNK * NCH];          // 4 MB (chunk-level max)
__device__ float   g_pool[NCH];

// ---------------- PTX helpers ----------------
__device__ __forceinline__ uint32_t smem_u32(const void* p) {
    uint32_t a;
    asm("{ .reg .u64 t; cvta.to.shared.u64 t, %1; cvt.u32.u64 %0, t; }" : "=r"(a) : "l"(p));
    return a;
}

__device__ __forceinline__ void cp16(uint32_t dst, const void* src) {
    asm volatile("cp.async.cg.shared.global [%0], [%1], 16;" :: "r"(dst), "l"(src));
}
#define CP_COMMIT() asm volatile("cp.async.commit_group;" ::: "memory")
#define CP_WAIT(n)  asm volatile("cp.async.wait_group %0;" :: "n"(n) : "memory")

__device__ __forceinline__ void ldsm_x4(uint32_t& r0, uint32_t& r1, uint32_t& r2, uint32_t& r3,
                                        uint32_t addr) {
    asm volatile("ldmatrix.sync.aligned.m8n8.x4.shared.b16 {%0,%1,%2,%3}, [%4];"
                 : "=r"(r0), "=r"(r1), "=r"(r2), "=r"(r3) : "r"(addr));
}
__device__ __forceinline__ void ldsm_x4_t(uint32_t& r0, uint32_t& r1, uint32_t& r2, uint32_t& r3,
                                          uint32_t addr) {
    asm volatile("ldmatrix.sync.aligned.m8n8.x4.trans.shared.b16 {%0,%1,%2,%3}, [%4];"
                 : "=r"(r0), "=r"(r1), "=r"(r2), "=r"(r3) : "r"(addr));
}

__device__ __forceinline__ void mma_f16(float& c0, float& c1, float& c2, float& c3,
                                        uint32_t a0, uint32_t a1, uint32_t a2, uint32_t a3,
                                        uint32_t b0, uint32_t b1) {
    asm volatile(
        "mma.sync.aligned.m16n8k16.row.col.f32.f16.f16.f32 "
        "{%0,%1,%2,%3}, {%4,%5,%6,%7}, {%8,%9}, {%0,%1,%2,%3};"
        : "+f"(c0), "+f"(c1), "+f"(c2), "+f"(c3)
        : "r"(a0), "r"(a1), "r"(a2), "r"(a3), "r"(b0), "r"(b1));
}

__device__ __forceinline__ float sigm(float x) { return 1.0f / (1.0f + expf(-x)); }

// ---------------- fp16 pack helpers ----------------
__device__ __forceinline__ uint2 pack_h4(float4 a) {
    __half2 p0 = __floats2half2_rn(a.x, a.y);
    __half2 p1 = __floats2half2_rn(a.z, a.w);
    uint2 r;
    r.x = *reinterpret_cast<uint32_t*>(&p0);
    r.y = *reinterpret_cast<uint32_t*>(&p1);
    return r;
}
__device__ __forceinline__ uint2 split_h4(float4 a, float4& rest) {
    __half h0 = __float2half_rn(a.x);
    __half h1 = __float2half_rn(a.y);
    __half h2 = __float2half_rn(a.z);
    __half h3 = __float2half_rn(a.w);
    rest.x = a.x - __half2float(h0);
    rest.y = a.y - __half2float(h1);
    rest.z = a.z - __half2float(h2);
    rest.w = a.w - __half2float(h3);
    __half2 p0 = __halves2half2(h0, h1);
    __half2 p1 = __halves2half2(h2, h3);
    uint2 r;
    r.x = *reinterpret_cast<uint32_t*>(&p0);
    r.y = *reinterpret_cast<uint32_t*>(&p1);
    return r;
}

// ---------------- embedding gather + fused fp16 cast ----------------
__global__ void gather_kernel(const int* __restrict__ x,
                              const float* __restrict__ embed,
                              float* __restrict__ h,
                              __half* __restrict__ ah) {
    size_t idx = (size_t)blockIdx.x * blockDim.x + threadIdx.x;
    int m = (int)(idx >> 7);
    int j = (int)(idx & 127);
    int row = x[m];
    float4 a = reinterpret_cast<const float4*>(embed)[(size_t)row * 128 + j];
    reinterpret_cast<float4*>(h)[idx] = a;
    reinterpret_cast<uint2*>(ah)[idx] = pack_h4(a);
}

// ---------------- weight conversion: fp32 -> fp16 hi/lo ----------------
__global__ void convert_kernel(const float* __restrict__ src,
                               __half* __restrict__ hi,
                               __half* __restrict__ lo) {
    size_t idx = (size_t)blockIdx.x * blockDim.x + threadIdx.x;
    float4 a = reinterpret_cast<const float4*>(src)[idx];
    float4 rest;
    uint2 hw = split_h4(a, rest);
    uint2 lw = pack_h4(rest);
    reinterpret_cast<uint2*>(hi)[idx] = hw;
    reinterpret_cast<uint2*>(lo)[idx] = lw;
}

// ---------------- GEMM mainloop body (TERMS = 2 for xt cols, 1 for gate cols) ----------------
template<int TERMS>
__device__ __forceinline__ void gemm_body(
    const __half* __restrict__ Ah,
    const __half* __restrict__ Bhi, const __half* __restrict__ Blo,
    int m0, int n0, uint32_t sbase, int tid, float acc[4][4][4])
{
    const int lane = tid & 31;
    const int wid = tid >> 5;
    const int wm = wid >> 2;
    const int wn = wid & 3;
    const int lrow = lane & 15;
    const int lcol8 = (lane >> 4) * 8;

    auto load_stage = [&](int kt, int st) {
        uint32_t sb = sbase + st * ST_BYTES;
        int kk = kt * BK;
#pragma unroll
        for (int c = 0; c < 2; c++) {
            int ci = tid + c * 256;
            int am = ci >> 2, ak = ci & 3;
            cp16(sb + ST_A + am * A_PITCH + ak * 16,
                 Ah + (size_t)(m0 + am) * K_SZ + kk + ak * 8);
            int bk = ci >> 4, bq = ci & 15;
            cp16(sb + ST_B_HI + bk * B_PITCH + bq * 16,
                 Bhi + (size_t)(kk + bk) * N3 + n0 + bq * 8);
            if (TERMS == 2)
                cp16(sb + ST_B_LO + bk * B_PITCH + bq * 16,
                     Blo + (size_t)(kk + bk) * N3 + n0 + bq * 8);
        }
    };

    // prologue: stages 0..2
    load_stage(0, 0); CP_COMMIT();
    load_stage(1, 1); CP_COMMIT();
    load_stage(2, 2); CP_COMMIT();

    for (int kt = 0; kt < KT_ITERS; kt++) {
        const int st = kt % STAGES;
        CP_WAIT(2);
        __syncthreads();   // stage kt readable; slot (kt+3)%4 = (kt-1)%4 drained by program order

        if (kt + 3 < KT_ITERS) load_stage(kt + 3, (kt + 3) % STAGES);
        CP_COMMIT();       // unconditional: keeps wait_group counting aligned

        const uint32_t sb = sbase + st * ST_BYTES;
        const uint32_t sA  = sb + ST_A + (wm * 64 + lrow) * A_PITCH;
        const uint32_t sBh = sb + ST_B_HI + lrow * B_PITCH + (wn * 32 + lcol8) * 2;
        const uint32_t sBl = sb + ST_B_LO + lrow * B_PITCH + (wn * 32 + lcol8) * 2;

#pragma unroll
        for (int k16 = 0; k16 < 2; k16++) {
            uint32_t bh[2][4], bl[2][4];
#pragma unroll
            for (int nj = 0; nj < 2; nj++) {
                uint32_t bo = k16 * 16 * B_PITCH + nj * 16 * 2;
                ldsm_x4_t(bh[nj][0], bh[nj][1], bh[nj][2], bh[nj][3], sBh + bo);
                if (TERMS == 2)
                    ldsm_x4_t(bl[nj][0], bl[nj][1], bl[nj][2], bl[nj][3], sBl + bo);
            }
#pragma unroll
            for (int mi = 0; mi < 4; mi++) {
                uint32_t ah[4];
                uint32_t ao = mi * 16 * A_PITCH + (k16 * 16 + lcol8) * 2;
                ldsm_x4(ah[0], ah[1], ah[2], ah[3], sA + ao);
#pragma unroll
                for (int n8 = 0; n8 < 4; n8++) {
                    float* c = acc[mi][n8];
                    uint32_t b0h = bh[n8 >> 1][(n8 & 1) * 2], b1h = bh[n8 >> 1][(n8 & 1) * 2 + 1];
                    mma_f16(c[0], c[1], c[2], c[3], ah[0], ah[1], ah[2], ah[3], b0h, b1h);
                    if (TERMS == 2) {
                        uint32_t b0l = bl[n8 >> 1][(n8 & 1) * 2], b1l = bl[n8 >> 1][(n8 & 1) * 2 + 1];
                        mma_f16(c[0], c[1], c[2], c[3], ah[0], ah[1], ah[2], ah[3], b0l, b1l);
                    }
                }
            }
        }
    }
}

// ---------------- fp16 HMMA GEMM: 128x128x512, mixed-term split, fused gate ----------------
__global__ __launch_bounds__(256, 2) void gemm_mma_kernel(
    const __half* __restrict__ Ah,
    const __half* __restrict__ Bhi, const __half* __restrict__ Blo,
    const float* __restrict__ bias,   // 1024 (f then r)
    float* __restrict__ U)
{
    extern __shared__ __align__(1024) char smem[];
    __shared__ float s_bias[BN];

    const int tid = threadIdx.x;
    const int lane = tid & 31;
    const int wid = tid >> 5;
    const int wm = wid >> 2;
    const int wn = wid & 3;
    const int ntile = blockIdx.x;
    const int mtile = blockIdx.y;
    const int n0 = ntile * BN;
    const int m0 = mtile * BM;
    const bool gate = (n0 >= 512);

    if (tid < BN) s_bias[tid] = gate ? bias[n0 - 512 + tid] : 0.0f;

    const uint32_t sbase = smem_u32(smem);

    float acc[4][4][4];
#pragma unroll
    for (int i = 0; i < 4; i++)
#pragma unroll
        for (int j = 0; j < 4; j++)
#pragma unroll
            for (int q = 0; q < 4; q++) acc[i][j][q] = 0.0f;

    if (!gate) gemm_body<2>(Ah, Bhi, Blo, m0, n0, sbase, tid, acc);
    else       gemm_body<1>(Ah, Bhi, Blo, m0, n0, sbase, tid, acc);

    // ---- epilogue: bias + sigmoid on gate tiles, float2 stores ----
    const int g = lane >> 2;
    const int tig = lane & 3;
#pragma unroll
    for (int mi = 0; mi < 4; mi++) {
        int row = m0 + wm * 64 + mi * 16 + g;
#pragma unroll
        for (int n8 = 0; n8 < 4; n8++) {
            int coll = wn * 32 + n8 * 8 + tig * 2;
            float v0 = acc[mi][n8][0], v1 = acc[mi][n8][1];
            float v2 = acc[mi][n8][2], v3 = acc[mi][n8][3];
            if (gate) {
                float b0 = s_bias[coll], b1 = s_bias[coll + 1];
                v0 = sigm(v0 + b0); v1 = sigm(v1 + b1);
                v2 = sigm(v2 + b0); v3 = sigm(v3 + b1);
            }
            float2 p0 = {v0, v1}, p1 = {v2, v3};
            *reinterpret_cast<float2*>(&U[(size_t)row * N3 + n0 + coll]) = p0;
            *reinterpret_cast<float2*>(&U[(size_t)(row + 8) * N3 + n0 + coll]) = p1;
        }
    }
}

// ---------------- scan pass A: per-chunk affine composition ----------------
__global__ void scan_passA(const float* __restrict__ U,
                           float* __restrict__ Ac, float* __restrict__ Bc) {
    int idx = blockIdx.x * blockDim.x + threadIdx.x;
    int ch = idx & (NCH - 1);
    int chunk = idx >> 14;
    int b = ch >> 9;
    int h = ch & 511;
    const float* fp = U + ((size_t)(chunk * CHUNK * B_SZ + b)) * N3 + 512 + h;
    float Aa = 1.0f, Bb = 0.0f;
#pragma unroll 8
    for (int i = 0; i < CHUNK; i++) {
        float f  = fp[0];
        float xt = fp[-512];
        Bb = f * Bb + (1.0f - f) * xt;
        Aa *= f;
        fp += (size_t)B_SZ * N3;
    }
    Ac[idx] = Aa;
    Bc[idx] = Bb;
}

// ---------------- scan pass B: prefix over chunks ----------------
__global__ void scan_passB(const float* __restrict__ Ac,
                           const float* __restrict__ Bc,
                           float* __restrict__ ci) {
    int ch = blockIdx.x * blockDim.x + threadIdx.x;
    float c = 0.0f;
#pragma unroll 8
    for (int k = 0; k < NCHUNK; k++) {
        ci[k * NCH + ch] = c;
        c = Ac[k * NCH + ch] * c + Bc[k * NCH + ch];
    }
}

// ---------------- scan pass C: rescan + highway output ----------------
// mode 0: write hout fp32 + fp16 cast (feeds next layer GEMM)
// mode 1: final layer -> emit per-chunk max only (no hout store)
__global__ void scan_passC(const float* __restrict__ U,
                           const float* __restrict__ ci,
                           const float* __restrict__ hin,
                           float* __restrict__ hout,
                           __half* __restrict__ ah_out,
                           float* __restrict__ pm,
                           int mode) {
    int idx = blockIdx.x * blockDim.x + threadIdx.x;
    int ch = idx & (NCH - 1);
    int chunk = idx >> 14;
    int b = ch >> 9;
    int h = ch & 511;
    size_t m0 = (size_t)(chunk * CHUNK * B_SZ + b);
    const float* fp = U + m0 * N3 + 512 + h;
    size_t hoff = m0 * H_SZ + h;
    float c = ci[idx];
    float mx = -INFINITY;
#pragma unroll 4
    for (int i = 0; i < CHUNK; i++) {
        float f  = fp[0];
        float xt = fp[-512];
        float r  = fp[512];
        float hv = hin[hoff];
        c = f * c + (1.0f - f) * xt;
        float o = r * tanhf(c) + (1.0f - r) * hv;
        if (mode == 0) {
            hout[hoff] = o;
            ah_out[hoff] = __float2half_rn(o);
        } else {
            mx = fmaxf(mx, o);
        }
        fp += (size_t)B_SZ * N3;
        hoff += (size_t)B_SZ * H_SZ;
    }
    if (mode == 1) pm[idx] = mx;
}

// ---------------- pool reduce over chunks (tanh monotonic: tanh after max) ----------------
__global__ void pool_reduce(const float* __restrict__ pm, float* __restrict__ pool) {
    int ch = blockIdx.x * blockDim.x + threadIdx.x;
    float mx = -INFINITY;
#pragma unroll 8
    for (int s = 0; s < NCHUNK; s++) mx = fmaxf(mx, pm[s * NCH + ch]);
    pool[ch] = tanhf(tanhf(mx));
}

// ---------------- tiny classifier ----------------
__global__ void classifier_kernel(const float* __restrict__ pool,
                                  const float* __restrict__ Wc,
                                  const float* __restrict__ bc,
                                  float* __restrict__ out) {
    int tid = threadIdx.x;
    int b = tid / C_SZ;
    int c = tid % C_SZ;
    float s = bc[c];
    const float* p = pool + b * H_SZ;
#pragma unroll 8
    for (int h = 0; h < H_SZ; h++) s += p[h] * Wc[h * C_SZ + c];
    out[b * C_SZ + c] = s;
}

// ---------------- launch ----------------
extern "C" void kernel_launch(void* const* d_in, const int* in_sizes, int n_in,
                              void* d_out, int out_size) {
    const int*   x     = (const int*)d_in[0];
    const float* embed = (const float*)d_in[1];
    const float* W     = (const float*)d_in[2]; // (L, 512, 1536)
    const float* b     = (const float*)d_in[3]; // (L, 1024)
    const float* Wc    = (const float*)d_in[4]; // (512, 10)
    const float* bc    = (const float*)d_in[5]; // (10,)
    float* out = (float*)d_out;

    float *hA, *hB, *U, *Ac, *Bc, *ci, *pm, *pool;
    __half *Ah, *Bhi, *Blo;
    cudaGetSymbolAddress((void**)&hA, g_hA);
    cudaGetSymbolAddress((void**)&hB, g_hB);
    cudaGetSymbolAddress((void**)&U,  g_U);
    cudaGetSymbolAddress((void**)&Ah, g_Ah);
    cudaGetSymbolAddress((void**)&Bhi, g_Bhi);
    cudaGetSymbolAddress((void**)&Blo, g_Blo);
    cudaGetSymbolAddress((void**)&Ac, g_Ac);
    cudaGetSymbolAddress((void**)&Bc, g_Bc);
    cudaGetSymbolAddress((void**)&ci, g_ci);
    cudaGetSymbolAddress((void**)&pm, g_pm);
    cudaGetSymbolAddress((void**)&pool, g_pool);

    cudaFuncSetAttribute(gemm_mma_kernel, cudaFuncAttributeMaxDynamicSharedMemorySize, DYN_SMEM);

    // weight conversion (both layers at once)
    convert_kernel<<<(2 * K_SZ * N3 / 4) / 256, 256>>>(W, Bhi, Blo);

    // embedding gather (emits fp32 h + fp16 A for layer-0 GEMM)
    gather_kernel<<<(M_SZ * 128) / 256, 256>>>(x, embed, hA, Ah);

    dim3 gemmGrid(NTILES, MTILES); // x fastest -> 12 CTAs share one A tile via L2
    const int scanBlocks = (NCHUNK * NCH) / 256;

    // layer 0: hA -> hB (passC emits fp16 A for layer-1 GEMM)
    gemm_mma_kernel<<<gemmGrid, 256, DYN_SMEM>>>(Ah, Bhi, Blo, b, U);
    scan_passA<<<scanBlocks, 256>>>(U, Ac, Bc);
    scan_passB<<<NCH / 256, 256>>>(Ac, Bc, ci);
    scan_passC<<<scanBlocks, 256>>>(U, ci, hA, hB, Ah, pm, 0);

    // layer 1: hB -> (pooled chunk maxima)
    gemm_mma_kernel<<<gemmGrid, 256, DYN_SMEM>>>(Ah, Bhi + (size_t)K_SZ * N3,
                                                 Blo + (size_t)K_SZ * N3, b + 2 * H_SZ, U);
    scan_passA<<<scanBlocks, 256>>>(U, Ac, Bc);
    scan_passB<<<NCH / 256, 256>>>(Ac, Bc, ci);
    scan_passC<<<scanBlocks, 256>>>(U, ci, hB, hA, Ah, pm, 1);

    // pool + classifier
    pool_reduce<<<NCH / 256, 256>>>(pm, pool);
    classifier_kernel<<<1, B_SZ * C_SZ>>>(pool, Wc, bc, out);
}

// round 8
// speedup vs baseline: 3.9924x; 1.1648x over previous
#include <cuda_runtime.h>
#include <cuda_fp16.h>
#include <math.h>
#include <stdint.h>

#define S_LEN   2048
#define B_SZ    32
#define D_SZ    512
#define H_SZ    512
#define N3      1536            // 3*H
#define M_SZ    (S_LEN * B_SZ)  // 65536
#define K_SZ    512
#define CHUNK   32
#define NCHUNK  (S_LEN / CHUNK) // 64
#define NCH     (B_SZ * H_SZ)   // 16384
#define C_SZ    10

// ---------------- GEMM tiling ----------------
#define BM 128
#define BN 128
#define BK 32
#define KT_ITERS (K_SZ / BK)    // 16
#define STAGES 4
#define MTILES (M_SZ / BM)      // 512
#define NTILES (N3 / BN)        // 12

// smem pitches (bytes), padded for conflict-free ldmatrix
#define A_PITCH 80              // 32 fp16 = 64B + 16B pad
#define B_PITCH 272             // 128 fp16 = 256B + 16B pad
#define ST_A    0
#define ST_B    (BM * A_PITCH)                 // 10240
#define ST_BYTES (BM * A_PITCH + BK * B_PITCH) // 18944
#define DYN_SMEM (STAGES * ST_BYTES)           // 75776 -> 2 CTAs/SM (regs bind)

// ---------------- scratch (device globals: allocation-free rule) ----------------
__device__ float   g_hA[(size_t)M_SZ * H_SZ];   // 128 MB
__device__ float   g_hB[(size_t)M_SZ * H_SZ];   // 128 MB
__device__ __half  g_U [(size_t)M_SZ * N3];     // 192 MB (fp16 U)
__device__ __half  g_Ah[(size_t)M_SZ * K_SZ];   // 64 MB  (fp16 A)
__device__ __half  g_Bh[2 * K_SZ * N3];         // 3 MB   (fp16 W)
__device__ float   g_Ac[NCHUNK * NCH];
__device__ float   g_Bc[NCHUNK * NCH];
__device__ float   g_ci[NCHUNK * NCH];
__device__ float   g_pm[NCHUNK * NCH];          // 4 MB (chunk-level max)
__device__ float   g_pool[NCH];

// ---------------- PTX helpers ----------------
__device__ __forceinline__ uint32_t smem_u32(const void* p) {
    uint32_t a;
    asm("{ .reg .u64 t; cvta.to.shared.u64 t, %1; cvt.u32.u64 %0, t; }" : "=r"(a) : "l"(p));
    return a;
}

__device__ __forceinline__ void cp16(uint32_t dst, const void* src) {
    asm volatile("cp.async.cg.shared.global [%0], [%1], 16;" :: "r"(dst), "l"(src));
}
#define CP_COMMIT() asm volatile("cp.async.commit_group;" ::: "memory")
#define CP_WAIT(n)  asm volatile("cp.async.wait_group %0;" :: "n"(n) : "memory")

__device__ __forceinline__ void ldsm_x4(uint32_t& r0, uint32_t& r1, uint32_t& r2, uint32_t& r3,
                                        uint32_t addr) {
    asm volatile("ldmatrix.sync.aligned.m8n8.x4.shared.b16 {%0,%1,%2,%3}, [%4];"
                 : "=r"(r0), "=r"(r1), "=r"(r2), "=r"(r3) : "r"(addr));
}
__device__ __forceinline__ void ldsm_x4_t(uint32_t& r0, uint32_t& r1, uint32_t& r2, uint32_t& r3,
                                          uint32_t addr) {
    asm volatile("ldmatrix.sync.aligned.m8n8.x4.trans.shared.b16 {%0,%1,%2,%3}, [%4];"
                 : "=r"(r0), "=r"(r1), "=r"(r2), "=r"(r3) : "r"(addr));
}

__device__ __forceinline__ void mma_f16(float& c0, float& c1, float& c2, float& c3,
                                        uint32_t a0, uint32_t a1, uint32_t a2, uint32_t a3,
                                        uint32_t b0, uint32_t b1) {
    asm volatile(
        "mma.sync.aligned.m16n8k16.row.col.f32.f16.f16.f32 "
        "{%0,%1,%2,%3}, {%4,%5,%6,%7}, {%8,%9}, {%0,%1,%2,%3};"
        : "+f"(c0), "+f"(c1), "+f"(c2), "+f"(c3)
        : "r"(a0), "r"(a1), "r"(a2), "r"(a3), "r"(b0), "r"(b1));
}

__device__ __forceinline__ float sigm(float x) { return 1.0f / (1.0f + expf(-x)); }

// ---------------- fp16 pack helpers ----------------
__device__ __forceinline__ uint2 pack_h4(float4 a) {
    __half2 p0 = __floats2half2_rn(a.x, a.y);
    __half2 p1 = __floats2half2_rn(a.z, a.w);
    uint2 r;
    r.x = *reinterpret_cast<uint32_t*>(&p0);
    r.y = *reinterpret_cast<uint32_t*>(&p1);
    return r;
}

// ---------------- embedding gather + fused fp16 cast ----------------
__global__ void gather_kernel(const int* __restrict__ x,
                              const float* __restrict__ embed,
                              float* __restrict__ h,
                              __half* __restrict__ ah) {
    size_t idx = (size_t)blockIdx.x * blockDim.x + threadIdx.x;
    int m = (int)(idx >> 7);
    int j = (int)(idx & 127);
    int row = x[m];
    float4 a = reinterpret_cast<const float4*>(embed)[(size_t)row * 128 + j];
    reinterpret_cast<float4*>(h)[idx] = a;
    reinterpret_cast<uint2*>(ah)[idx] = pack_h4(a);
}

// ---------------- weight conversion: fp32 -> fp16 ----------------
__global__ void convert_kernel(const float* __restrict__ src,
                               __half* __restrict__ dst) {
    size_t idx = (size_t)blockIdx.x * blockDim.x + threadIdx.x;
    float4 a = reinterpret_cast<const float4*>(src)[idx];
    reinterpret_cast<uint2*>(dst)[idx] = pack_h4(a);
}

// ---------------- fp16 HMMA GEMM: 128x128x512, single term, fused gate ----------------
__global__ __launch_bounds__(256, 2) void gemm_mma_kernel(
    const __half* __restrict__ Ah,
    const __half* __restrict__ Bh,
    const float* __restrict__ bias,   // 1024 (f then r)
    __half* __restrict__ U)
{
    extern __shared__ __align__(1024) char smem[];
    __shared__ float s_bias[BN];

    const int tid = threadIdx.x;
    const int lane = tid & 31;
    const int wid = tid >> 5;
    const int wm = wid >> 2;
    const int wn = wid & 3;
    const int ntile = blockIdx.x;
    const int mtile = blockIdx.y;
    const int n0 = ntile * BN;
    const int m0 = mtile * BM;
    const bool gate = (n0 >= 512);

    if (tid < BN) s_bias[tid] = gate ? bias[n0 - 512 + tid] : 0.0f;

    const uint32_t sbase = smem_u32(smem);
    const int lrow = lane & 15;
    const int lcol8 = (lane >> 4) * 8;

    // A: 128 rows x 4 chunks = 512 cp16 ; B: 32 rows x 16 chunks = 512 cp16.
    // BOTH are covered by the two c-iterations (ci = 0..511). (R7 bug: B was
    // gated to c==0, leaving B rows 16..31 unloaded.)
    auto load_stage = [&](int kt, int st) {
        uint32_t sb = sbase + st * ST_BYTES;
        int kk = kt * BK;
#pragma unroll
        for (int c = 0; c < 2; c++) {
            int ci = tid + c * 256;
            int am = ci >> 2, ak = ci & 3;
            cp16(sb + ST_A + am * A_PITCH + ak * 16,
                 Ah + (size_t)(m0 + am) * K_SZ + kk + ak * 8);
            int bk = ci >> 4, bq = ci & 15;
            cp16(sb + ST_B + bk * B_PITCH + bq * 16,
                 Bh + (size_t)(kk + bk) * N3 + n0 + bq * 8);
        }
    };

    float acc[4][4][4];
#pragma unroll
    for (int i = 0; i < 4; i++)
#pragma unroll
        for (int j = 0; j < 4; j++)
#pragma unroll
            for (int q = 0; q < 4; q++) acc[i][j][q] = 0.0f;

    // prologue: stages 0..2
    load_stage(0, 0); CP_COMMIT();
    load_stage(1, 1); CP_COMMIT();
    load_stage(2, 2); CP_COMMIT();

    for (int kt = 0; kt < KT_ITERS; kt++) {
        const int st = kt % STAGES;
        CP_WAIT(2);
        __syncthreads();

        if (kt + 3 < KT_ITERS) load_stage(kt + 3, (kt + 3) % STAGES);
        CP_COMMIT();       // unconditional: keeps wait_group counting aligned

        const uint32_t sb = sbase + st * ST_BYTES;
        const uint32_t sA = sb + ST_A + (wm * 64 + lrow) * A_PITCH;
        const uint32_t sB = sb + ST_B + lrow * B_PITCH + (wn * 32 + lcol8) * 2;

#pragma unroll
        for (int k16 = 0; k16 < 2; k16++) {
            uint32_t bh[2][4];
#pragma unroll
            for (int nj = 0; nj < 2; nj++) {
                uint32_t bo = k16 * 16 * B_PITCH + nj * 16 * 2;
                ldsm_x4_t(bh[nj][0], bh[nj][1], bh[nj][2], bh[nj][3], sB + bo);
            }
#pragma unroll
            for (int mi = 0; mi < 4; mi++) {
                uint32_t ah[4];
                uint32_t ao = mi * 16 * A_PITCH + (k16 * 16 + lcol8) * 2;
                ldsm_x4(ah[0], ah[1], ah[2], ah[3], sA + ao);
#pragma unroll
                for (int n8 = 0; n8 < 4; n8++) {
                    float* c = acc[mi][n8];
                    mma_f16(c[0], c[1], c[2], c[3], ah[0], ah[1], ah[2], ah[3],
                            bh[n8 >> 1][(n8 & 1) * 2], bh[n8 >> 1][(n8 & 1) * 2 + 1]);
                }
            }
        }
    }

    // ---- epilogue: bias + sigmoid on gate tiles, half2 stores ----
    const int g = lane >> 2;
    const int tig = lane & 3;
#pragma unroll
    for (int mi = 0; mi < 4; mi++) {
        int row = m0 + wm * 64 + mi * 16 + g;
#pragma unroll
        for (int n8 = 0; n8 < 4; n8++) {
            int coll = wn * 32 + n8 * 8 + tig * 2;
            float v0 = acc[mi][n8][0], v1 = acc[mi][n8][1];
            float v2 = acc[mi][n8][2], v3 = acc[mi][n8][3];
            if (gate) {
                float b0 = s_bias[coll], b1 = s_bias[coll + 1];
                v0 = sigm(v0 + b0); v1 = sigm(v1 + b1);
                v2 = sigm(v2 + b0); v3 = sigm(v3 + b1);
            }
            __half2 p0 = __floats2half2_rn(v0, v1);
            __half2 p1 = __floats2half2_rn(v2, v3);
            *reinterpret_cast<__half2*>(&U[(size_t)row * N3 + n0 + coll]) = p0;
            *reinterpret_cast<__half2*>(&U[(size_t)(row + 8) * N3 + n0 + coll]) = p1;
        }
    }
}

// ---------------- scan pass A: per-chunk affine composition ----------------
__global__ void scan_passA(const __half* __restrict__ U,
                           float* __restrict__ Ac, float* __restrict__ Bc) {
    int idx = blockIdx.x * blockDim.x + threadIdx.x;
    int ch = idx & (NCH - 1);
    int chunk = idx >> 14;
    int b = ch >> 9;
    int h = ch & 511;
    const __half* fp = U + ((size_t)(chunk * CHUNK * B_SZ + b)) * N3 + 512 + h;
    float Aa = 1.0f, Bb = 0.0f;
#pragma unroll 8
    for (int i = 0; i < CHUNK; i++) {
        float f  = __half2float(fp[0]);
        float xt = __half2float(fp[-512]);
        Bb = f * Bb + (1.0f - f) * xt;
        Aa *= f;
        fp += (size_t)B_SZ * N3;
    }
    Ac[idx] = Aa;
    Bc[idx] = Bb;
}

// ---------------- scan pass B: prefix over chunks ----------------
__global__ void scan_passB(const float* __restrict__ Ac,
                           const float* __restrict__ Bc,
                           float* __restrict__ ci) {
    int ch = blockIdx.x * blockDim.x + threadIdx.x;
    float c = 0.0f;
#pragma unroll 8
    for (int k = 0; k < NCHUNK; k++) {
        ci[k * NCH + ch] = c;
        c = Ac[k * NCH + ch] * c + Bc[k * NCH + ch];
    }
}

// ---------------- scan pass C: rescan + highway output ----------------
// mode 0: write hout fp32 + fp16 cast (feeds next layer GEMM)
// mode 1: final layer -> emit per-chunk max only (no hout store)
__global__ void scan_passC(const __half* __restrict__ U,
                           const float* __restrict__ ci,
                           const float* __restrict__ hin,
                           float* __restrict__ hout,
                           __half* __restrict__ ah_out,
                           float* __restrict__ pm,
                           int mode) {
    int idx = blockIdx.x * blockDim.x + threadIdx.x;
    int ch = idx & (NCH - 1);
    int chunk = idx >> 14;
    int b = ch >> 9;
    int h = ch & 511;
    size_t m0 = (size_t)(chunk * CHUNK * B_SZ + b);
    const __half* fp = U + m0 * N3 + 512 + h;
    size_t hoff = m0 * H_SZ + h;
    float c = ci[idx];
    float mx = -INFINITY;
#pragma unroll 4
    for (int i = 0; i < CHUNK; i++) {
        float f  = __half2float(fp[0]);
        float xt = __half2float(fp[-512]);
        float r  = __half2float(fp[512]);
        float hv = hin[hoff];
        c = f * c + (1.0f - f) * xt;
        float o = r * tanhf(c) + (1.0f - r) * hv;
        if (mode == 0) {
            hout[hoff] = o;
            ah_out[hoff] = __float2half_rn(o);
        } else {
            mx = fmaxf(mx, o);
        }
        fp += (size_t)B_SZ * N3;
        hoff += (size_t)B_SZ * H_SZ;
    }
    if (mode == 1) pm[idx] = mx;
}

// ---------------- pool reduce over chunks (tanh monotonic: tanh after max) ----------------
__global__ void pool_reduce(const float* __restrict__ pm, float* __restrict__ pool) {
    int ch = blockIdx.x * blockDim.x + threadIdx.x;
    float mx = -INFINITY;
#pragma unroll 8
    for (int s = 0; s < NCHUNK; s++) mx = fmaxf(mx, pm[s * NCH + ch]);
    pool[ch] = tanhf(tanhf(mx));
}

// ---------------- tiny classifier ----------------
__global__ void classifier_kernel(const float* __restrict__ pool,
                                  const float* __restrict__ Wc,
                                  const float* __restrict__ bc,
                                  float* __restrict__ out) {
    int tid = threadIdx.x;
    int b = tid / C_SZ;
    int c = tid % C_SZ;
    float s = bc[c];
    const float* p = pool + b * H_SZ;
#pragma unroll 8
    for (int h = 0; h < H_SZ; h++) s += p[h] * Wc[h * C_SZ + c];
    out[b * C_SZ + c] = s;
}

// ---------------- launch ----------------
extern "C" void kernel_launch(void* const* d_in, const int* in_sizes, int n_in,
                              void* d_out, int out_size) {
    const int*   x     = (const int*)d_in[0];
    const float* embed = (const float*)d_in[1];
    const float* W     = (const float*)d_in[2]; // (L, 512, 1536)
    const float* b     = (const float*)d_in[3]; // (L, 1024)
    const float* Wc    = (const float*)d_in[4]; // (512, 10)
    const float* bc    = (const float*)d_in[5]; // (10,)
    float* out = (float*)d_out;

    float *hA, *hB, *Ac, *Bc, *ci, *pm, *pool;
    __half *U, *Ah, *Bh;
    cudaGetSymbolAddress((void**)&hA, g_hA);
    cudaGetSymbolAddress((void**)&hB, g_hB);
    cudaGetSymbolAddress((void**)&U,  g_U);
    cudaGetSymbolAddress((void**)&Ah, g_Ah);
    cudaGetSymbolAddress((void**)&Bh, g_Bh);
    cudaGetSymbolAddress((void**)&Ac, g_Ac);
    cudaGetSymbolAddress((void**)&Bc, g_Bc);
    cudaGetSymbolAddress((void**)&ci, g_ci);
    cudaGetSymbolAddress((void**)&pm, g_pm);
    cudaGetSymbolAddress((void**)&pool, g_pool);

    cudaFuncSetAttribute(gemm_mma_kernel, cudaFuncAttributeMaxDynamicSharedMemorySize, DYN_SMEM);

    // weight conversion (both layers at once)
    convert_kernel<<<(2 * K_SZ * N3 / 4) / 256, 256>>>(W, Bh);

    // embedding gather (emits fp32 h + fp16 A for layer-0 GEMM)
    gather_kernel<<<(M_SZ * 128) / 256, 256>>>(x, embed, hA, Ah);

    dim3 gemmGrid(NTILES, MTILES); // x fastest -> 12 CTAs share one A tile via L2
    const int scanBlocks = (NCHUNK * NCH) / 256;

    // layer 0: hA -> hB (passC emits fp16 A for layer-1 GEMM)
    gemm_mma_kernel<<<gemmGrid, 256, DYN_SMEM>>>(Ah, Bh, b, U);
    scan_passA<<<scanBlocks, 256>>>(U, Ac, Bc);
    scan_passB<<<NCH / 256, 256>>>(Ac, Bc, ci);
    scan_passC<<<scanBlocks, 256>>>(U, ci, hA, hB, Ah, pm, 0);

    // layer 1: hB -> (pooled chunk maxima)
    gemm_mma_kernel<<<gemmGrid, 256, DYN_SMEM>>>(Ah, Bh + (size_t)K_SZ * N3, b + 2 * H_SZ, U);
    scan_passA<<<scanBlocks, 256>>>(U, Ac, Bc);
    scan_passB<<<NCH / 256, 256>>>(Ac, Bc, ci);
    scan_passC<<<scanBlocks, 256>>>(U, ci, hB, hA, Ah, pm, 1);

    // pool + classifier
    pool_reduce<<<NCH / 256, 256>>>(pm, pool);
    classifier_kernel<<<1, B_SZ * C_SZ>>>(pool, Wc, bc, out);
}

// round 9
// speedup vs baseline: 4.5820x; 1.1477x over previous
#include <cuda_runtime.h>
#include <cuda_fp16.h>
#include <math.h>
#include <stdint.h>

#define S_LEN   2048
#define B_SZ    32
#define D_SZ    512
#define H_SZ    512
#define N3      1536            // 3*H
#define M_SZ    (S_LEN * B_SZ)  // 65536
#define K_SZ    512
#define CHUNK   32
#define NCHUNK  (S_LEN / CHUNK) // 64
#define NCH     (B_SZ * H_SZ)   // 16384
#define C_SZ    10

// ---------------- GEMM tiling ----------------
#define BM 128
#define BN 128
#define BK 32
#define KT_ITERS (K_SZ / BK)    // 16
#define STAGES 5
#define MTILES (M_SZ / BM)      // 512
#define NTILES (N3 / BN)        // 12

// smem pitches (bytes), padded for conflict-free ldmatrix
#define A_PITCH 80              // 32 fp16 = 64B + 16B pad
#define B_PITCH 272             // 128 fp16 = 256B + 16B pad
#define ST_A    0
#define ST_B    (BM * A_PITCH)                 // 10240
#define ST_BYTES (BM * A_PITCH + BK * B_PITCH) // 18944
#define DYN_SMEM (STAGES * ST_BYTES)           // 94720 -> 2 CTAs/SM (regs bind)

// ---------------- scratch (device globals: allocation-free rule) ----------------
__device__ __half  g_U  [(size_t)M_SZ * N3];    // 192 MB (fp16 U)
__device__ __half  g_AhA[(size_t)M_SZ * K_SZ];  // 64 MB  (fp16 h, buffer A)
__device__ __half  g_AhB[(size_t)M_SZ * K_SZ];  // 64 MB  (fp16 h, buffer B)
__device__ __half  g_Bh [2 * K_SZ * N3];        // 3 MB   (fp16 W)
__device__ float   g_Ac[NCHUNK * NCH];
__device__ float   g_Bc[NCHUNK * NCH];
__device__ float   g_ci[NCHUNK * NCH];
__device__ float   g_pm[NCHUNK * NCH];          // 4 MB (chunk-level max)
__device__ float   g_pool[NCH];

// ---------------- PTX helpers ----------------
__device__ __forceinline__ uint32_t smem_u32(const void* p) {
    uint32_t a;
    asm("{ .reg .u64 t; cvta.to.shared.u64 t, %1; cvt.u32.u64 %0, t; }" : "=r"(a) : "l"(p));
    return a;
}

__device__ __forceinline__ void cp16(uint32_t dst, const void* src) {
    asm volatile("cp.async.cg.shared.global [%0], [%1], 16;" :: "r"(dst), "l"(src));
}
#define CP_COMMIT() asm volatile("cp.async.commit_group;" ::: "memory")
#define CP_WAIT(n)  asm volatile("cp.async.wait_group %0;" :: "n"(n) : "memory")

__device__ __forceinline__ void ldsm_x4(uint32_t& r0, uint32_t& r1, uint32_t& r2, uint32_t& r3,
                                        uint32_t addr) {
    asm volatile("ldmatrix.sync.aligned.m8n8.x4.shared.b16 {%0,%1,%2,%3}, [%4];"
                 : "=r"(r0), "=r"(r1), "=r"(r2), "=r"(r3) : "r"(addr));
}
__device__ __forceinline__ void ldsm_x4_t(uint32_t& r0, uint32_t& r1, uint32_t& r2, uint32_t& r3,
                                          uint32_t addr) {
    asm volatile("ldmatrix.sync.aligned.m8n8.x4.trans.shared.b16 {%0,%1,%2,%3}, [%4];"
                 : "=r"(r0), "=r"(r1), "=r"(r2), "=r"(r3) : "r"(addr));
}

__device__ __forceinline__ void mma_f16(float& c0, float& c1, float& c2, float& c3,
                                        uint32_t a0, uint32_t a1, uint32_t a2, uint32_t a3,
                                        uint32_t b0, uint32_t b1) {
    asm volatile(
        "mma.sync.aligned.m16n8k16.row.col.f32.f16.f16.f32 "
        "{%0,%1,%2,%3}, {%4,%5,%6,%7}, {%8,%9}, {%0,%1,%2,%3};"
        : "+f"(c0), "+f"(c1), "+f"(c2), "+f"(c3)
        : "r"(a0), "r"(a1), "r"(a2), "r"(a3), "r"(b0), "r"(b1));
}

__device__ __forceinline__ float sigm(float x) { return 1.0f / (1.0f + expf(-x)); }

// ---------------- fp16 pack helpers ----------------
__device__ __forceinline__ uint2 pack_h4(float4 a) {
    __half2 p0 = __floats2half2_rn(a.x, a.y);
    __half2 p1 = __floats2half2_rn(a.z, a.w);
    uint2 r;
    r.x = *reinterpret_cast<uint32_t*>(&p0);
    r.y = *reinterpret_cast<uint32_t*>(&p1);
    return r;
}

// ---------------- embedding gather -> fp16 h ----------------
__global__ void gather_kernel(const int* __restrict__ x,
                              const float* __restrict__ embed,
                              __half* __restrict__ ah) {
    size_t idx = (size_t)blockIdx.x * blockDim.x + threadIdx.x;
    int m = (int)(idx >> 7);
    int j = (int)(idx & 127);
    int row = x[m];
    float4 a = reinterpret_cast<const float4*>(embed)[(size_t)row * 128 + j];
    reinterpret_cast<uint2*>(ah)[idx] = pack_h4(a);
}

// ---------------- weight conversion: fp32 -> fp16 ----------------
__global__ void convert_kernel(const float* __restrict__ src,
                               __half* __restrict__ dst) {
    size_t idx = (size_t)blockIdx.x * blockDim.x + threadIdx.x;
    float4 a = reinterpret_cast<const float4*>(src)[idx];
    reinterpret_cast<uint2*>(dst)[idx] = pack_h4(a);
}

// ---------------- fp16 HMMA GEMM: 128x128x512, single term, fused gate ----------------
__global__ __launch_bounds__(256, 2) void gemm_mma_kernel(
    const __half* __restrict__ Ah,
    const __half* __restrict__ Bh,
    const float* __restrict__ bias,   // 1024 (f then r)
    __half* __restrict__ U)
{
    extern __shared__ __align__(1024) char smem[];
    __shared__ float s_bias[BN];

    const int tid = threadIdx.x;
    const int lane = tid & 31;
    const int wid = tid >> 5;
    const int wm = wid >> 2;
    const int wn = wid & 3;
    const int ntile = blockIdx.x;
    const int mtile = blockIdx.y;
    const int n0 = ntile * BN;
    const int m0 = mtile * BM;
    const bool gate = (n0 >= 512);

    if (tid < BN) s_bias[tid] = gate ? bias[n0 - 512 + tid] : 0.0f;

    const uint32_t sbase = smem_u32(smem);
    const int lrow = lane & 15;
    const int lcol8 = (lane >> 4) * 8;

    // A: 128 rows x 4 chunks = 512 cp16 ; B: 32 rows x 16 chunks = 512 cp16.
    auto load_stage = [&](int kt, int st) {
        uint32_t sb = sbase + st * ST_BYTES;
        int kk = kt * BK;
#pragma unroll
        for (int c = 0; c < 2; c++) {
            int ci = tid + c * 256;
            int am = ci >> 2, ak = ci & 3;
            cp16(sb + ST_A + am * A_PITCH + ak * 16,
                 Ah + (size_t)(m0 + am) * K_SZ + kk + ak * 8);
            int bk = ci >> 4, bq = ci & 15;
            cp16(sb + ST_B + bk * B_PITCH + bq * 16,
                 Bh + (size_t)(kk + bk) * N3 + n0 + bq * 8);
        }
    };

    float acc[4][4][4];
#pragma unroll
    for (int i = 0; i < 4; i++)
#pragma unroll
        for (int j = 0; j < 4; j++)
#pragma unroll
            for (int q = 0; q < 4; q++) acc[i][j][q] = 0.0f;

    // prologue: stages 0..3
    load_stage(0, 0); CP_COMMIT();
    load_stage(1, 1); CP_COMMIT();
    load_stage(2, 2); CP_COMMIT();
    load_stage(3, 3); CP_COMMIT();

    for (int kt = 0; kt < KT_ITERS; kt++) {
        const int st = kt % STAGES;
        CP_WAIT(3);
        __syncthreads();   // stage kt readable by all; slot (kt+4)%5 = (kt-1)%5 drained

        if (kt + 4 < KT_ITERS) load_stage(kt + 4, (kt + 4) % STAGES);
        CP_COMMIT();       // unconditional: keeps wait_group counting aligned

        const uint32_t sb = sbase + st * ST_BYTES;
        const uint32_t sA = sb + ST_A + (wm * 64 + lrow) * A_PITCH;
        const uint32_t sB = sb + ST_B + lrow * B_PITCH + (wn * 32 + lcol8) * 2;

#pragma unroll
        for (int k16 = 0; k16 < 2; k16++) {
            uint32_t bh[2][4];
#pragma unroll
            for (int nj = 0; nj < 2; nj++) {
                uint32_t bo = k16 * 16 * B_PITCH + nj * 16 * 2;
                ldsm_x4_t(bh[nj][0], bh[nj][1], bh[nj][2], bh[nj][3], sB + bo);
            }
#pragma unroll
            for (int mi = 0; mi < 4; mi++) {
                uint32_t ah[4];
                uint32_t ao = mi * 16 * A_PITCH + (k16 * 16 + lcol8) * 2;
                ldsm_x4(ah[0], ah[1], ah[2], ah[3], sA + ao);
#pragma unroll
                for (int n8 = 0; n8 < 4; n8++) {
                    float* c = acc[mi][n8];
                    mma_f16(c[0], c[1], c[2], c[3], ah[0], ah[1], ah[2], ah[3],
                            bh[n8 >> 1][(n8 & 1) * 2], bh[n8 >> 1][(n8 & 1) * 2 + 1]);
                }
            }
        }
    }

    // ---- epilogue: bias + sigmoid on gate tiles, half2 stores ----
    const int g = lane >> 2;
    const int tig = lane & 3;
#pragma unroll
    for (int mi = 0; mi < 4; mi++) {
        int row = m0 + wm * 64 + mi * 16 + g;
#pragma unroll
        for (int n8 = 0; n8 < 4; n8++) {
            int coll = wn * 32 + n8 * 8 + tig * 2;
            float v0 = acc[mi][n8][0], v1 = acc[mi][n8][1];
            float v2 = acc[mi][n8][2], v3 = acc[mi][n8][3];
            if (gate) {
                float b0 = s_bias[coll], b1 = s_bias[coll + 1];
                v0 = sigm(v0 + b0); v1 = sigm(v1 + b1);
                v2 = sigm(v2 + b0); v3 = sigm(v3 + b1);
            }
            __half2 p0 = __floats2half2_rn(v0, v1);
            __half2 p1 = __floats2half2_rn(v2, v3);
            *reinterpret_cast<__half2*>(&U[(size_t)row * N3 + n0 + coll]) = p0;
            *reinterpret_cast<__half2*>(&U[(size_t)(row + 8) * N3 + n0 + coll]) = p1;
        }
    }
}

// ---------------- scan pass A: per-chunk affine composition ----------------
__global__ void scan_passA(const __half* __restrict__ U,
                           float* __restrict__ Ac, float* __restrict__ Bc) {
    int idx = blockIdx.x * blockDim.x + threadIdx.x;
    int ch = idx & (NCH - 1);
    int chunk = idx >> 14;
    int b = ch >> 9;
    int h = ch & 511;
    const __half* fp = U + ((size_t)(chunk * CHUNK * B_SZ + b)) * N3 + 512 + h;
    float Aa = 1.0f, Bb = 0.0f;
#pragma unroll 8
    for (int i = 0; i < CHUNK; i++) {
        float f  = __half2float(fp[0]);
        float xt = __half2float(fp[-512]);
        Bb = f * Bb + (1.0f - f) * xt;
        Aa *= f;
        fp += (size_t)B_SZ * N3;
    }
    Ac[idx] = Aa;
    Bc[idx] = Bb;
}

// ---------------- scan pass B: prefix over chunks ----------------
__global__ void scan_passB(const float* __restrict__ Ac,
                           const float* __restrict__ Bc,
                           float* __restrict__ ci) {
    int ch = blockIdx.x * blockDim.x + threadIdx.x;
    float c = 0.0f;
#pragma unroll 8
    for (int k = 0; k < NCHUNK; k++) {
        ci[k * NCH + ch] = c;
        c = Ac[k * NCH + ch] * c + Bc[k * NCH + ch];
    }
}

// ---------------- scan pass C: rescan + highway output (all fp16 h) ----------------
// mode 0: write fp16 h_out (feeds next layer GEMM + next passC hin)
// mode 1: final layer -> emit per-chunk max only
__global__ void scan_passC(const __half* __restrict__ U,
                           const float* __restrict__ ci,
                           const __half* __restrict__ hin,
                           __half* __restrict__ hout,
                           float* __restrict__ pm,
                           int mode) {
    int idx = blockIdx.x * blockDim.x + threadIdx.x;
    int ch = idx & (NCH - 1);
    int chunk = idx >> 14;
    int b = ch >> 9;
    int h = ch & 511;
    size_t m0 = (size_t)(chunk * CHUNK * B_SZ + b);
    const __half* fp = U + m0 * N3 + 512 + h;
    size_t hoff = m0 * H_SZ + h;
    float c = ci[idx];
    float mx = -INFINITY;
#pragma unroll 4
    for (int i = 0; i < CHUNK; i++) {
        float f  = __half2float(fp[0]);
        float xt = __half2float(fp[-512]);
        float r  = __half2float(fp[512]);
        float hv = __half2float(hin[hoff]);
        c = f * c + (1.0f - f) * xt;
        float o = r * tanhf(c) + (1.0f - r) * hv;
        if (mode == 0) {
            hout[hoff] = __float2half_rn(o);
        } else {
            mx = fmaxf(mx, o);
        }
        fp += (size_t)B_SZ * N3;
        hoff += (size_t)B_SZ * H_SZ;
    }
    if (mode == 1) pm[idx] = mx;
}

// ---------------- pool reduce over chunks (tanh monotonic: tanh after max) ----------------
__global__ void pool_reduce(const float* __restrict__ pm, float* __restrict__ pool) {
    int ch = blockIdx.x * blockDim.x + threadIdx.x;
    float mx = -INFINITY;
#pragma unroll 8
    for (int s = 0; s < NCHUNK; s++) mx = fmaxf(mx, pm[s * NCH + ch]);
    pool[ch] = tanhf(tanhf(mx));
}

// ---------------- tiny classifier ----------------
__global__ void classifier_kernel(const float* __restrict__ pool,
                                  const float* __restrict__ Wc,
                                  const float* __restrict__ bc,
                                  float* __restrict__ out) {
    int tid = threadIdx.x;
    int b = tid / C_SZ;
    int c = tid % C_SZ;
    float s = bc[c];
    const float* p = pool + b * H_SZ;
#pragma unroll 8
    for (int h = 0; h < H_SZ; h++) s += p[h] * Wc[h * C_SZ + c];
    out[b * C_SZ + c] = s;
}

// ---------------- launch ----------------
extern "C" void kernel_launch(void* const* d_in, const int* in_sizes, int n_in,
                              void* d_out, int out_size) {
    const int*   x     = (const int*)d_in[0];
    const float* embed = (const float*)d_in[1];
    const float* W     = (const float*)d_in[2]; // (L, 512, 1536)
    const float* b     = (const float*)d_in[3]; // (L, 1024)
    const float* Wc    = (const float*)d_in[4]; // (512, 10)
    const float* bc    = (const float*)d_in[5]; // (10,)
    float* out = (float*)d_out;

    float *Ac, *Bc, *ci, *pm, *pool;
    __half *U, *AhA, *AhB, *Bh;
    cudaGetSymbolAddress((void**)&U,   g_U);
    cudaGetSymbolAddress((void**)&AhA, g_AhA);
    cudaGetSymbolAddress((void**)&AhB, g_AhB);
    cudaGetSymbolAddress((void**)&Bh,  g_Bh);
    cudaGetSymbolAddress((void**)&Ac,  g_Ac);
    cudaGetSymbolAddress((void**)&Bc,  g_Bc);
    cudaGetSymbolAddress((void**)&ci,  g_ci);
    cudaGetSymbolAddress((void**)&pm,  g_pm);
    cudaGetSymbolAddress((void**)&pool, g_pool);

    cudaFuncSetAttribute(gemm_mma_kernel, cudaFuncAttributeMaxDynamicSharedMemorySize, DYN_SMEM);

    // weight conversion (both layers at once)
    convert_kernel<<<(2 * K_SZ * N3 / 4) / 256, 256>>>(W, Bh);

    // embedding gather -> fp16 h (buffer A)
    gather_kernel<<<(M_SZ * 128) / 256, 256>>>(x, embed, AhA);

    dim3 gemmGrid(NTILES, MTILES); // x fastest -> 12 CTAs share one A tile via L2
    const int scanBlocks = (NCHUNK * NCH) / 256;

    // layer 0: AhA -> AhB
    gemm_mma_kernel<<<gemmGrid, 256, DYN_SMEM>>>(AhA, Bh, b, U);
    scan_passA<<<scanBlocks, 256>>>(U, Ac, Bc);
    scan_passB<<<NCH / 256, 256>>>(Ac, Bc, ci);
    scan_passC<<<scanBlocks, 256>>>(U, ci, AhA, AhB, pm, 0);

    // layer 1: AhB -> (pooled chunk maxima)
    gemm_mma_kernel<<<gemmGrid, 256, DYN_SMEM>>>(AhB, Bh + (size_t)K_SZ * N3, b + 2 * H_SZ, U);
    scan_passA<<<scanBlocks, 256>>>(U, Ac, Bc);
    scan_passB<<<NCH / 256, 256>>>(Ac, Bc, ci);
    scan_passC<<<scanBlocks, 256>>>(U, ci, AhB, AhA, pm, 1);

    // pool + classifier
    pool_reduce<<<NCH / 256, 256>>>(pm, pool);
    classifier_kernel<<<1, B_SZ * C_SZ>>>(pool, Wc, bc, out);
}